// round 2
// baseline (speedup 1.0000x reference)
#include <cuda_runtime.h>

#define BATCH 4
#define SEQ   4096
#define EMB   1024
#define HEAD  64
#define H3    192
#define MTOT  (BATCH*SEQ)   // 16384

// Scratch (allocation-free rule: device globals)
__device__ __align__(16) float g_qkv[MTOT * H3];   // 12.6 MB
__device__ __align__(16) float g_ctx[MTOT * HEAD]; //  4.2 MB

// ---------------------------------------------------------------------------
// Kernel 1: QKV projection.  C[M=16384, N=192] = x[M, 1024] * W[1024, 192] + b
// Block tile 128x64, BK=16, 256 threads, 8x4 per thread.
// ---------------------------------------------------------------------------
__global__ __launch_bounds__(256) void qkv_gemm(const float* __restrict__ x,
                                                const float* __restrict__ W,
                                                const float* __restrict__ bias) {
    __shared__ float As[16][132];   // [k][m], padded
    __shared__ float Bs[16][64];    // [k][n]

    const int bm = blockIdx.x * 128;
    const int bn = blockIdx.y * 64;
    const int tid = threadIdx.x;
    const int tx = tid & 15;        // n
    const int ty = tid >> 4;        // m

    float acc[8][4];
#pragma unroll
    for (int i = 0; i < 8; i++)
#pragma unroll
        for (int j = 0; j < 4; j++) acc[i][j] = 0.f;

    const float* xb = x + (size_t)bm * EMB;

    for (int k0 = 0; k0 < EMB; k0 += 16) {
        // A tile: 128 rows x 16 k  (512 float4 loads, 2 per thread), store transposed
#pragma unroll
        for (int i = 0; i < 2; i++) {
            int idx = tid + i * 256;
            int row = idx >> 2;
            int kq  = (idx & 3) * 4;
            float4 v = *reinterpret_cast<const float4*>(xb + (size_t)row * EMB + k0 + kq);
            As[kq + 0][row] = v.x;
            As[kq + 1][row] = v.y;
            As[kq + 2][row] = v.z;
            As[kq + 3][row] = v.w;
        }
        // B tile: 16 k-rows x 64 n (1 float4 per thread)
        {
            int krow = tid >> 4;          // 0..15
            int nq   = (tid & 15) * 4;    // 0..60
            float4 v = *reinterpret_cast<const float4*>(W + (size_t)(k0 + krow) * H3 + bn + nq);
            *reinterpret_cast<float4*>(&Bs[krow][nq]) = v;
        }
        __syncthreads();

#pragma unroll
        for (int kk = 0; kk < 16; kk++) {
            float4 a0 = *reinterpret_cast<const float4*>(&As[kk][ty * 8]);
            float4 a1 = *reinterpret_cast<const float4*>(&As[kk][ty * 8 + 4]);
            float4 b4 = *reinterpret_cast<const float4*>(&Bs[kk][tx * 4]);
            float a[8] = {a0.x, a0.y, a0.z, a0.w, a1.x, a1.y, a1.z, a1.w};
            float bb[4] = {b4.x, b4.y, b4.z, b4.w};
#pragma unroll
            for (int i = 0; i < 8; i++)
#pragma unroll
                for (int j = 0; j < 4; j++) acc[i][j] += a[i] * bb[j];
        }
        __syncthreads();
    }

#pragma unroll
    for (int i = 0; i < 8; i++) {
        int row = bm + ty * 8 + i;
        int col = bn + tx * 4;
        float4 res;
        res.x = acc[i][0] + bias[col + 0];
        res.y = acc[i][1] + bias[col + 1];
        res.z = acc[i][2] + bias[col + 2];
        res.w = acc[i][3] + bias[col + 3];
        *reinterpret_cast<float4*>(&g_qkv[(size_t)row * H3 + col]) = res;
    }
}

// ---------------------------------------------------------------------------
// Kernel 2: flash attention. Block = 64 queries; loop over 64 KV tiles of 64.
// 256 threads, each owns a 4x4 micro-tile (rows = ty*4.., cols/dims = tx*4..).
// Online softmax, row reductions via 16-lane shuffles.
// ---------------------------------------------------------------------------
#define SROW 68                       // smem row stride (floats): mult of 4 -> float4-aligned
#define ATT_SMEM (4 * 64 * SROW * 4)  // 4 tiles of [64][68] floats = 69632 B

__global__ __launch_bounds__(256) void attn_kernel() {
    extern __shared__ float sm[];
    float* sQt = sm;                    // [d][r]  Q^T, pre-scaled
    float* sKt = sm + 1 * 64 * SROW;    // [d][c]  K^T
    float* sPt = sm + 2 * 64 * SROW;    // [c][r]  P^T
    float* sV  = sm + 3 * 64 * SROW;    // [c][d]

    const int b   = blockIdx.y;
    const int q0  = blockIdx.x * 64;
    const int tid = threadIdx.x;
    const int tx  = tid & 15;
    const int ty  = tid >> 4;
    const int r0  = ty * 4;
    const int c0  = tx * 4;
    const float scale = 0.125f;   // 1/sqrt(64)

    // Load Q tile transposed + scaled
    {
        int r  = tid >> 2;
        int d0 = (tid & 3) * 16;
        const float* qp = g_qkv + (size_t)(b * SEQ + q0 + r) * H3 + d0;
#pragma unroll
        for (int i = 0; i < 16; i += 4) {
            float4 v = *reinterpret_cast<const float4*>(qp + i);
            sQt[(d0 + i + 0) * SROW + r] = v.x * scale;
            sQt[(d0 + i + 1) * SROW + r] = v.y * scale;
            sQt[(d0 + i + 2) * SROW + r] = v.z * scale;
            sQt[(d0 + i + 3) * SROW + r] = v.w * scale;
        }
    }

    float o[4][4];
    float m_i[4], l_i[4];
#pragma unroll
    for (int i = 0; i < 4; i++) {
        m_i[i] = -1e30f;
        l_i[i] = 0.f;
#pragma unroll
        for (int j = 0; j < 4; j++) o[i][j] = 0.f;
    }

    for (int kv0 = 0; kv0 < SEQ; kv0 += 64) {
        __syncthreads();   // prev-iter PV reads of sPt/sV done; sQt load done (iter 0)
        // Load K (transposed) and V (direct)
        {
            int c  = tid >> 2;
            int d0 = (tid & 3) * 16;
            const float* kp = g_qkv + (size_t)(b * SEQ + kv0 + c) * H3 + HEAD + d0;
            const float* vp = g_qkv + (size_t)(b * SEQ + kv0 + c) * H3 + 2 * HEAD + d0;
#pragma unroll
            for (int i = 0; i < 16; i += 4) {
                float4 kv4 = *reinterpret_cast<const float4*>(kp + i);
                sKt[(d0 + i + 0) * SROW + c] = kv4.x;
                sKt[(d0 + i + 1) * SROW + c] = kv4.y;
                sKt[(d0 + i + 2) * SROW + c] = kv4.z;
                sKt[(d0 + i + 3) * SROW + c] = kv4.w;
                float4 vv4 = *reinterpret_cast<const float4*>(vp + i);
                *reinterpret_cast<float4*>(&sV[c * SROW + d0 + i]) = vv4;
            }
        }
        __syncthreads();

        // S = Q K^T  (64x64x64)
        float s[4][4];
#pragma unroll
        for (int i = 0; i < 4; i++)
#pragma unroll
            for (int j = 0; j < 4; j++) s[i][j] = 0.f;

#pragma unroll 4
        for (int kk = 0; kk < 64; kk++) {
            float4 a4 = *reinterpret_cast<const float4*>(&sQt[kk * SROW + r0]);
            float4 b4 = *reinterpret_cast<const float4*>(&sKt[kk * SROW + c0]);
            float a[4] = {a4.x, a4.y, a4.z, a4.w};
            float bb[4] = {b4.x, b4.y, b4.z, b4.w};
#pragma unroll
            for (int i = 0; i < 4; i++)
#pragma unroll
                for (int j = 0; j < 4; j++) s[i][j] += a[i] * bb[j];
        }

        // Online softmax (per query row; 16 tx-lanes share a row)
#pragma unroll
        for (int i = 0; i < 4; i++) {
            float mt = fmaxf(fmaxf(s[i][0], s[i][1]), fmaxf(s[i][2], s[i][3]));
#pragma unroll
            for (int msk = 1; msk < 16; msk <<= 1)
                mt = fmaxf(mt, __shfl_xor_sync(0xffffffffu, mt, msk));
            float mnew = fmaxf(m_i[i], mt);
            float corr = __expf(m_i[i] - mnew);
            float rs = 0.f;
#pragma unroll
            for (int j = 0; j < 4; j++) {
                s[i][j] = __expf(s[i][j] - mnew);
                rs += s[i][j];
            }
#pragma unroll
            for (int msk = 1; msk < 16; msk <<= 1)
                rs += __shfl_xor_sync(0xffffffffu, rs, msk);
            l_i[i] = l_i[i] * corr + rs;
            m_i[i] = mnew;
#pragma unroll
            for (int j = 0; j < 4; j++) o[i][j] *= corr;
        }

        // Write P^T (readers of sKt are done: sync above was the load sync —
        // sKt reads happened after it; the __syncthreads below orders P writes
        // before PV reads, and the loop-top sync protects sKt reuse)
#pragma unroll
        for (int i = 0; i < 4; i++)
#pragma unroll
            for (int j = 0; j < 4; j++)
                sPt[(c0 + j) * SROW + (r0 + i)] = s[i][j];
        __syncthreads();

        // O += P V  (64x64x64)
#pragma unroll 4
        for (int kk = 0; kk < 64; kk++) {
            float4 a4 = *reinterpret_cast<const float4*>(&sPt[kk * SROW + r0]);
            float4 b4 = *reinterpret_cast<const float4*>(&sV[kk * SROW + c0]);
            float a[4] = {a4.x, a4.y, a4.z, a4.w};
            float bb[4] = {b4.x, b4.y, b4.z, b4.w};
#pragma unroll
            for (int i = 0; i < 4; i++)
#pragma unroll
                for (int j = 0; j < 4; j++) o[i][j] += a[i] * bb[j];
        }
    }

    // Epilogue: normalize and store ctx
#pragma unroll
    for (int i = 0; i < 4; i++) {
        float inv = 1.f / l_i[i];
        int row = b * SEQ + q0 + r0 + i;
        float4 res;
        res.x = o[i][0] * inv;
        res.y = o[i][1] * inv;
        res.z = o[i][2] * inv;
        res.w = o[i][3] * inv;
        *reinterpret_cast<float4*>(&g_ctx[(size_t)row * HEAD + c0]) = res;
    }
}

// ---------------------------------------------------------------------------
// Kernel 3: output projection. out[M=16384, 1024] = ctx[M, 64] * W_out[64, 1024] + b
// Block tile 64x64, full K=64 in one pass, 256 threads, 4x4 per thread.
// ---------------------------------------------------------------------------
__global__ __launch_bounds__(256) void out_gemm(const float* __restrict__ Wout,
                                                const float* __restrict__ bout,
                                                float* __restrict__ out) {
    __shared__ float sAt[64][68];   // [k][m]  ctx^T
    __shared__ float sB[64][68];    // [k][n]

    const int bm = blockIdx.x * 64;
    const int bn = blockIdx.y * 64;
    const int tid = threadIdx.x;
    const int tx = tid & 15;
    const int ty = tid >> 4;

    // ctx tile transposed
    {
        int r  = tid >> 2;
        int d0 = (tid & 3) * 16;
        const float* cp = g_ctx + (size_t)(bm + r) * HEAD + d0;
#pragma unroll
        for (int i = 0; i < 16; i += 4) {
            float4 v = *reinterpret_cast<const float4*>(cp + i);
            sAt[d0 + i + 0][r] = v.x;
            sAt[d0 + i + 1][r] = v.y;
            sAt[d0 + i + 2][r] = v.z;
            sAt[d0 + i + 3][r] = v.w;
        }
    }
    // W_out tile: rows 0..63 (all of K), cols bn..bn+63
    {
        int k  = tid >> 2;
        int n0 = (tid & 3) * 16;
        const float* wp = Wout + (size_t)k * EMB + bn + n0;
#pragma unroll
        for (int i = 0; i < 16; i += 4) {
            float4 v = *reinterpret_cast<const float4*>(wp + i);
            *reinterpret_cast<float4*>(&sB[k][n0 + i]) = v;
        }
    }
    __syncthreads();

    float acc[4][4];
#pragma unroll
    for (int i = 0; i < 4; i++)
#pragma unroll
        for (int j = 0; j < 4; j++) acc[i][j] = 0.f;

#pragma unroll 4
    for (int kk = 0; kk < 64; kk++) {
        float4 a4 = *reinterpret_cast<const float4*>(&sAt[kk][ty * 4]);
        float4 b4 = *reinterpret_cast<const float4*>(&sB[kk][tx * 4]);
        float a[4] = {a4.x, a4.y, a4.z, a4.w};
        float bb[4] = {b4.x, b4.y, b4.z, b4.w};
#pragma unroll
        for (int i = 0; i < 4; i++)
#pragma unroll
            for (int j = 0; j < 4; j++) acc[i][j] += a[i] * bb[j];
    }

#pragma unroll
    for (int i = 0; i < 4; i++) {
        int row = bm + ty * 4 + i;
        int col = bn + tx * 4;
        float4 res;
        res.x = acc[i][0] + bout[col + 0];
        res.y = acc[i][1] + bout[col + 1];
        res.z = acc[i][2] + bout[col + 2];
        res.w = acc[i][3] + bout[col + 3];
        *reinterpret_cast<float4*>(&out[(size_t)row * EMB + col]) = res;
    }
}

// ---------------------------------------------------------------------------
extern "C" void kernel_launch(void* const* d_in, const int* in_sizes, int n_in,
                              void* d_out, int out_size) {
    const float* x     = (const float*)d_in[0];
    const float* W_qkv = (const float*)d_in[1];
    const float* b_qkv = (const float*)d_in[2];
    const float* W_out = (const float*)d_in[3];
    const float* b_out = (const float*)d_in[4];
    float* out = (float*)d_out;

    qkv_gemm<<<dim3(MTOT / 128, H3 / 64), 256>>>(x, W_qkv, b_qkv);

    cudaFuncSetAttribute(attn_kernel, cudaFuncAttributeMaxDynamicSharedMemorySize, ATT_SMEM);
    attn_kernel<<<dim3(SEQ / 64, BATCH), 256, ATT_SMEM>>>();

    out_gemm<<<dim3(MTOT / 64, EMB / 64), 256>>>(W_out, b_out, out);
}

// round 4
// speedup vs baseline: 1.9701x; 1.9701x over previous
#include <cuda_runtime.h>
#include <cstdint>

#define BATCH 4
#define SEQ   4096
#define EMB   1024
#define HEAD  64
#define H3    192
#define MTOT  (BATCH*SEQ)   // 16384

// Scratch (allocation-free rule: device globals)
__device__ __align__(16) float g_qkv[MTOT * H3];   // 12.6 MB
__device__ __align__(16) float g_ctx[MTOT * HEAD]; //  4.2 MB

// ---------------------------------------------------------------------------
// Kernel 1: QKV projection.  C[M=16384, N=192] = x[M, 1024] * W[1024, 192] + b
// ---------------------------------------------------------------------------
__global__ __launch_bounds__(256) void qkv_gemm(const float* __restrict__ x,
                                                const float* __restrict__ W,
                                                const float* __restrict__ bias) {
    __shared__ float As[16][132];   // [k][m], padded
    __shared__ float Bs[16][64];    // [k][n]

    const int bm = blockIdx.x * 128;
    const int bn = blockIdx.y * 64;
    const int tid = threadIdx.x;
    const int tx = tid & 15;        // n
    const int ty = tid >> 4;        // m

    float acc[8][4];
#pragma unroll
    for (int i = 0; i < 8; i++)
#pragma unroll
        for (int j = 0; j < 4; j++) acc[i][j] = 0.f;

    const float* xb = x + (size_t)bm * EMB;

    for (int k0 = 0; k0 < EMB; k0 += 16) {
#pragma unroll
        for (int i = 0; i < 2; i++) {
            int idx = tid + i * 256;
            int row = idx >> 2;
            int kq  = (idx & 3) * 4;
            float4 v = *reinterpret_cast<const float4*>(xb + (size_t)row * EMB + k0 + kq);
            As[kq + 0][row] = v.x;
            As[kq + 1][row] = v.y;
            As[kq + 2][row] = v.z;
            As[kq + 3][row] = v.w;
        }
        {
            int krow = tid >> 4;
            int nq   = (tid & 15) * 4;
            float4 v = *reinterpret_cast<const float4*>(W + (size_t)(k0 + krow) * H3 + bn + nq);
            *reinterpret_cast<float4*>(&Bs[krow][nq]) = v;
        }
        __syncthreads();

#pragma unroll
        for (int kk = 0; kk < 16; kk++) {
            float4 a0 = *reinterpret_cast<const float4*>(&As[kk][ty * 8]);
            float4 a1 = *reinterpret_cast<const float4*>(&As[kk][ty * 8 + 4]);
            float4 b4 = *reinterpret_cast<const float4*>(&Bs[kk][tx * 4]);
            float a[8] = {a0.x, a0.y, a0.z, a0.w, a1.x, a1.y, a1.z, a1.w};
            float bb[4] = {b4.x, b4.y, b4.z, b4.w};
#pragma unroll
            for (int i = 0; i < 8; i++)
#pragma unroll
                for (int j = 0; j < 4; j++) acc[i][j] += a[i] * bb[j];
        }
        __syncthreads();
    }

#pragma unroll
    for (int i = 0; i < 8; i++) {
        int row = bm + ty * 8 + i;
        int col = bn + tx * 4;
        float4 res;
        res.x = acc[i][0] + bias[col + 0];
        res.y = acc[i][1] + bias[col + 1];
        res.z = acc[i][2] + bias[col + 2];
        res.w = acc[i][3] + bias[col + 3];
        *reinterpret_cast<float4*>(&g_qkv[(size_t)row * H3 + col]) = res;
    }
}

// ---------------------------------------------------------------------------
// Kernel 2: flash attention on the tensor pipe (tf32 mma.sync m16n8k8).
// Block = 128 queries (8 warps x m16). KV tiles of 64. Online softmax in
// base-2 (scale folds in log2e). Q fragments register-resident (tf32).
// K stored [kv][d], V stored transposed [d][kv]; stride 68 -> conflict-free
// B-fragment LDS. P goes through a per-warp-private SMEM strip (__syncwarp only).
// ---------------------------------------------------------------------------
#define BQ    128
#define BKV   64
#define SROW2 68
#define ATT_SMEM2 (256 * SROW2 * 4)   // sK(64) + sVt(64) + sP(128) rows = 69632 B

__device__ __forceinline__ uint32_t f2tf32(float f) {
    uint32_t r;
    asm("cvt.rna.tf32.f32 %0, %1;" : "=r"(r) : "f"(f));
    return r;
}
__device__ __forceinline__ float exp2a(float x) {
    float y;
    asm("ex2.approx.f32 %0, %1;" : "=f"(y) : "f"(x));
    return y;
}
__device__ __forceinline__ void mma_tf32(float c[4], const uint32_t a[4],
                                         uint32_t b0, uint32_t b1) {
    asm volatile(
        "mma.sync.aligned.m16n8k8.row.col.f32.tf32.tf32.f32 "
        "{%0,%1,%2,%3}, {%4,%5,%6,%7}, {%8,%9}, {%0,%1,%2,%3};\n"
        : "+f"(c[0]), "+f"(c[1]), "+f"(c[2]), "+f"(c[3])
        : "r"(a[0]), "r"(a[1]), "r"(a[2]), "r"(a[3]), "r"(b0), "r"(b1));
}

__global__ __launch_bounds__(256, 2) void attn_tc() {
    extern __shared__ float sm2[];
    float* sK  = sm2;                   // [64 kv][68]  (tf32-rounded)
    float* sVt = sm2 + 64 * SROW2;      // [64 d][68 kv] (tf32-rounded, transposed)
    float* sP  = sm2 + 128 * SROW2;     // [128 q][68]  per-warp strips

    const int b    = blockIdx.y;
    const int q0   = blockIdx.x * BQ;
    const int tid  = threadIdx.x;
    const int w    = tid >> 5;
    const int lane = tid & 31;
    const int ly   = lane >> 2;   // 0..7
    const int lx   = lane & 3;    // 0..3

    float* sPw = sP + w * 16 * SROW2;

    const float qscale = 0.125f * 1.44269504088896340736f;  // (1/sqrt(64)) * log2(e)

    // --- Q fragments, register-resident tf32 ---
    uint32_t Aq[8][4];
    {
        const float* qb = g_qkv + (size_t)(b * SEQ + q0 + w * 16) * H3;
#pragma unroll
        for (int ks = 0; ks < 8; ks++) {
            int c = ks * 8 + lx;
            Aq[ks][0] = f2tf32(qb[(size_t)(ly    ) * H3 + c    ] * qscale);
            Aq[ks][1] = f2tf32(qb[(size_t)(ly + 8) * H3 + c    ] * qscale);
            Aq[ks][2] = f2tf32(qb[(size_t)(ly    ) * H3 + c + 4] * qscale);
            Aq[ks][3] = f2tf32(qb[(size_t)(ly + 8) * H3 + c + 4] * qscale);
        }
    }

    float O[8][4];
    float mrow0 = -1e30f, mrow1 = -1e30f, lrow0 = 0.f, lrow1 = 0.f;
#pragma unroll
    for (int nb = 0; nb < 8; nb++)
#pragma unroll
        for (int j = 0; j < 4; j++) O[nb][j] = 0.f;

    for (int kv0 = 0; kv0 < SEQ; kv0 += BKV) {
        __syncthreads();  // all warps done with sK/sVt from previous iter
        // --- load K (direct) and V (transposed), tf32-rounded at store ---
        {
            int c  = tid >> 2;           // kv row 0..63
            int d0 = (tid & 3) * 16;     // d start
            const float* kp = g_qkv + (size_t)(b * SEQ + kv0 + c) * H3 + HEAD;
            const float* vp = kp + HEAD;
#pragma unroll
            for (int i = 0; i < 16; i += 4) {
                float4 k4 = *reinterpret_cast<const float4*>(kp + d0 + i);
                sK[c * SROW2 + d0 + i + 0] = __uint_as_float(f2tf32(k4.x));
                sK[c * SROW2 + d0 + i + 1] = __uint_as_float(f2tf32(k4.y));
                sK[c * SROW2 + d0 + i + 2] = __uint_as_float(f2tf32(k4.z));
                sK[c * SROW2 + d0 + i + 3] = __uint_as_float(f2tf32(k4.w));
                float4 v4 = *reinterpret_cast<const float4*>(vp + d0 + i);
                sVt[(d0 + i + 0) * SROW2 + c] = __uint_as_float(f2tf32(v4.x));
                sVt[(d0 + i + 1) * SROW2 + c] = __uint_as_float(f2tf32(v4.y));
                sVt[(d0 + i + 2) * SROW2 + c] = __uint_as_float(f2tf32(v4.z));
                sVt[(d0 + i + 3) * SROW2 + c] = __uint_as_float(f2tf32(v4.w));
            }
        }
        __syncthreads();

        // --- S = (Q*scale) K^T : 8 n-blocks x 8 k-steps ---
        float S[8][4];
#pragma unroll
        for (int nb = 0; nb < 8; nb++)
#pragma unroll
            for (int j = 0; j < 4; j++) S[nb][j] = 0.f;

#pragma unroll
        for (int ks = 0; ks < 8; ks++) {
#pragma unroll
            for (int nb = 0; nb < 8; nb++) {
                uint32_t b0 = __float_as_uint(sK[(nb * 8 + ly) * SROW2 + ks * 8 + lx]);
                uint32_t b1 = __float_as_uint(sK[(nb * 8 + ly) * SROW2 + ks * 8 + 4 + lx]);
                mma_tf32(S[nb], Aq[ks], b0, b1);
            }
        }

        // --- online softmax (base-2). Thread rows: ly (c0,c1), ly+8 (c2,c3). ---
        float mt0 = -1e30f, mt1 = -1e30f;
#pragma unroll
        for (int nb = 0; nb < 8; nb++) {
            mt0 = fmaxf(mt0, fmaxf(S[nb][0], S[nb][1]));
            mt1 = fmaxf(mt1, fmaxf(S[nb][2], S[nb][3]));
        }
        mt0 = fmaxf(mt0, __shfl_xor_sync(0xffffffffu, mt0, 1));
        mt0 = fmaxf(mt0, __shfl_xor_sync(0xffffffffu, mt0, 2));
        mt1 = fmaxf(mt1, __shfl_xor_sync(0xffffffffu, mt1, 1));
        mt1 = fmaxf(mt1, __shfl_xor_sync(0xffffffffu, mt1, 2));

        float mn0 = fmaxf(mrow0, mt0);
        float mn1 = fmaxf(mrow1, mt1);
        float corr0 = exp2a(mrow0 - mn0);
        float corr1 = exp2a(mrow1 - mn1);

        float rs0 = 0.f, rs1 = 0.f;
#pragma unroll
        for (int nb = 0; nb < 8; nb++) {
            S[nb][0] = exp2a(S[nb][0] - mn0);
            S[nb][1] = exp2a(S[nb][1] - mn0);
            S[nb][2] = exp2a(S[nb][2] - mn1);
            S[nb][3] = exp2a(S[nb][3] - mn1);
            rs0 += S[nb][0] + S[nb][1];
            rs1 += S[nb][2] + S[nb][3];
        }
        rs0 += __shfl_xor_sync(0xffffffffu, rs0, 1);
        rs0 += __shfl_xor_sync(0xffffffffu, rs0, 2);
        rs1 += __shfl_xor_sync(0xffffffffu, rs1, 1);
        rs1 += __shfl_xor_sync(0xffffffffu, rs1, 2);

        lrow0 = lrow0 * corr0 + rs0;
        lrow1 = lrow1 * corr1 + rs1;
        mrow0 = mn0;
        mrow1 = mn1;

#pragma unroll
        for (int nb = 0; nb < 8; nb++) {
            O[nb][0] *= corr0;
            O[nb][1] *= corr0;
            O[nb][2] *= corr1;
            O[nb][3] *= corr1;
        }

        // --- write P (tf32) into per-warp strip; C-layout cols are pairs ---
#pragma unroll
        for (int nb = 0; nb < 8; nb++) {
            uint2 p01 = make_uint2(f2tf32(S[nb][0]), f2tf32(S[nb][1]));
            *reinterpret_cast<uint2*>(&sPw[ly * SROW2 + nb * 8 + 2 * lx]) = p01;
            uint2 p23 = make_uint2(f2tf32(S[nb][2]), f2tf32(S[nb][3]));
            *reinterpret_cast<uint2*>(&sPw[(ly + 8) * SROW2 + nb * 8 + 2 * lx]) = p23;
        }
        __syncwarp();

        // --- O += P V : A from sPw, B from sVt ---
#pragma unroll
        for (int ks = 0; ks < 8; ks++) {
            uint32_t pa[4];
            pa[0] = __float_as_uint(sPw[(ly    ) * SROW2 + ks * 8 + lx]);
            pa[1] = __float_as_uint(sPw[(ly + 8) * SROW2 + ks * 8 + lx]);
            pa[2] = __float_as_uint(sPw[(ly    ) * SROW2 + ks * 8 + 4 + lx]);
            pa[3] = __float_as_uint(sPw[(ly + 8) * SROW2 + ks * 8 + 4 + lx]);
#pragma unroll
            for (int nb = 0; nb < 8; nb++) {
                uint32_t b0 = __float_as_uint(sVt[(nb * 8 + ly) * SROW2 + ks * 8 + lx]);
                uint32_t b1 = __float_as_uint(sVt[(nb * 8 + ly) * SROW2 + ks * 8 + 4 + lx]);
                mma_tf32(O[nb], pa, b0, b1);
            }
        }
    }

    // --- epilogue: normalize, store ctx ---
    float inv0 = 1.f / lrow0;
    float inv1 = 1.f / lrow1;
    int r0g = b * SEQ + q0 + w * 16 + ly;
#pragma unroll
    for (int nb = 0; nb < 8; nb++) {
        float2 v0 = make_float2(O[nb][0] * inv0, O[nb][1] * inv0);
        *reinterpret_cast<float2*>(&g_ctx[(size_t)r0g * HEAD + nb * 8 + 2 * lx]) = v0;
        float2 v1 = make_float2(O[nb][2] * inv1, O[nb][3] * inv1);
        *reinterpret_cast<float2*>(&g_ctx[(size_t)(r0g + 8) * HEAD + nb * 8 + 2 * lx]) = v1;
    }
}

// ---------------------------------------------------------------------------
// Kernel 3: output projection. out[M=16384, 1024] = ctx[M, 64] * W_out[64, 1024] + b
// ---------------------------------------------------------------------------
__global__ __launch_bounds__(256) void out_gemm(const float* __restrict__ Wout,
                                                const float* __restrict__ bout,
                                                float* __restrict__ out) {
    __shared__ float sAt[64][68];   // [k][m]  ctx^T
    __shared__ float sB[64][68];    // [k][n]

    const int bm = blockIdx.x * 64;
    const int bn = blockIdx.y * 64;
    const int tid = threadIdx.x;
    const int tx = tid & 15;
    const int ty = tid >> 4;

    {
        int r  = tid >> 2;
        int d0 = (tid & 3) * 16;
        const float* cp = g_ctx + (size_t)(bm + r) * HEAD + d0;
#pragma unroll
        for (int i = 0; i < 16; i += 4) {
            float4 v = *reinterpret_cast<const float4*>(cp + i);
            sAt[d0 + i + 0][r] = v.x;
            sAt[d0 + i + 1][r] = v.y;
            sAt[d0 + i + 2][r] = v.z;
            sAt[d0 + i + 3][r] = v.w;
        }
    }
    {
        int k  = tid >> 2;
        int n0 = (tid & 3) * 16;
        const float* wp = Wout + (size_t)k * EMB + bn + n0;
#pragma unroll
        for (int i = 0; i < 16; i += 4) {
            float4 v = *reinterpret_cast<const float4*>(wp + i);
            *reinterpret_cast<float4*>(&sB[k][n0 + i]) = v;
        }
    }
    __syncthreads();

    float acc[4][4];
#pragma unroll
    for (int i = 0; i < 4; i++)
#pragma unroll
        for (int j = 0; j < 4; j++) acc[i][j] = 0.f;

#pragma unroll 4
    for (int kk = 0; kk < 64; kk++) {
        float4 a4 = *reinterpret_cast<const float4*>(&sAt[kk][ty * 4]);
        float4 b4 = *reinterpret_cast<const float4*>(&sB[kk][tx * 4]);
        float a[4] = {a4.x, a4.y, a4.z, a4.w};
        float bb[4] = {b4.x, b4.y, b4.z, b4.w};
#pragma unroll
        for (int i = 0; i < 4; i++)
#pragma unroll
            for (int j = 0; j < 4; j++) acc[i][j] += a[i] * bb[j];
    }

#pragma unroll
    for (int i = 0; i < 4; i++) {
        int row = bm + ty * 4 + i;
        int col = bn + tx * 4;
        float4 res;
        res.x = acc[i][0] + bout[col + 0];
        res.y = acc[i][1] + bout[col + 1];
        res.z = acc[i][2] + bout[col + 2];
        res.w = acc[i][3] + bout[col + 3];
        *reinterpret_cast<float4*>(&out[(size_t)row * EMB + col]) = res;
    }
}

// ---------------------------------------------------------------------------
extern "C" void kernel_launch(void* const* d_in, const int* in_sizes, int n_in,
                              void* d_out, int out_size) {
    const float* x     = (const float*)d_in[0];
    const float* W_qkv = (const float*)d_in[1];
    const float* b_qkv = (const float*)d_in[2];
    const float* W_out = (const float*)d_in[3];
    const float* b_out = (const float*)d_in[4];
    float* out = (float*)d_out;

    qkv_gemm<<<dim3(MTOT / 128, H3 / 64), 256>>>(x, W_qkv, b_qkv);

    cudaFuncSetAttribute(attn_tc, cudaFuncAttributeMaxDynamicSharedMemorySize, ATT_SMEM2);
    attn_tc<<<dim3(SEQ / BQ, BATCH), 256, ATT_SMEM2>>>();

    out_gemm<<<dim3(MTOT / 64, EMB / 64), 256>>>(W_out, b_out, out);
}

// round 5
// speedup vs baseline: 2.6994x; 1.3702x over previous
#include <cuda_runtime.h>
#include <cuda_bf16.h>
#include <cstdint>

#define BATCH 4
#define SEQ   4096
#define EMB   1024
#define HEAD  64
#define H3    192
#define MTOT  (BATCH*SEQ)   // 16384

// Scratch (allocation-free rule: device globals)
__device__ __align__(16) float g_qkv[MTOT * H3];   // 12.6 MB
__device__ __align__(16) float g_ctx[MTOT * HEAD]; //  4.2 MB

// ---------------------------------------------------------------------------
// Common helpers
// ---------------------------------------------------------------------------
__device__ __forceinline__ uint32_t f2tf32(float f) {
    uint32_t r;
    asm("cvt.rna.tf32.f32 %0, %1;" : "=r"(r) : "f"(f));
    return r;
}
__device__ __forceinline__ float exp2a(float x) {
    float y;
    asm("ex2.approx.f32 %0, %1;" : "=f"(y) : "f"(x));
    return y;
}
__device__ __forceinline__ void mma_tf32(float c[4], const uint32_t a[4],
                                         uint32_t b0, uint32_t b1) {
    asm volatile(
        "mma.sync.aligned.m16n8k8.row.col.f32.tf32.tf32.f32 "
        "{%0,%1,%2,%3}, {%4,%5,%6,%7}, {%8,%9}, {%0,%1,%2,%3};\n"
        : "+f"(c[0]), "+f"(c[1]), "+f"(c[2]), "+f"(c[3])
        : "r"(a[0]), "r"(a[1]), "r"(a[2]), "r"(a[3]), "r"(b0), "r"(b1));
}
__device__ __forceinline__ void mma_bf16(float c[4], const uint32_t a[4],
                                         uint32_t b0, uint32_t b1) {
    asm volatile(
        "mma.sync.aligned.m16n8k16.row.col.f32.bf16.bf16.f32 "
        "{%0,%1,%2,%3}, {%4,%5,%6,%7}, {%8,%9}, {%0,%1,%2,%3};\n"
        : "+f"(c[0]), "+f"(c[1]), "+f"(c[2]), "+f"(c[3])
        : "r"(a[0]), "r"(a[1]), "r"(a[2]), "r"(a[3]), "r"(b0), "r"(b1));
}
// Split (x,y) into packed bf16x2 hi and lo parts: x ~= hi + lo (compensated).
__device__ __forceinline__ void split_pack(float x, float y,
                                           uint32_t& hi, uint32_t& lo) {
    __nv_bfloat16 hx = __float2bfloat16_rn(x);
    __nv_bfloat16 hy = __float2bfloat16_rn(y);
    __nv_bfloat16 lxx = __float2bfloat16_rn(x - __bfloat162float(hx));
    __nv_bfloat16 lyy = __float2bfloat16_rn(y - __bfloat162float(hy));
    __nv_bfloat162 h2 = __halves2bfloat162(hx, hy);
    __nv_bfloat162 l2 = __halves2bfloat162(lxx, lyy);
    hi = *reinterpret_cast<uint32_t*>(&h2);
    lo = *reinterpret_cast<uint32_t*>(&l2);
}

// ---------------------------------------------------------------------------
// Kernel 1: QKV projection on tensor pipe (bf16 3-term split, fp32-accurate).
// C[16384,192] = x[16384,1024] * W[1024,192] + b.  BM=128, BN=64, BK=32.
// 8 warps, each warp: 16 rows x 64 cols (8 n-blocks of m16n8k16).
// ---------------------------------------------------------------------------
#define QBM 128
#define QBN 64
#define QBK 32
#define QAST 20   // uint (bf16x2) row stride for A (16 used): 20*ly%32 distinct
#define QBST 20

__global__ __launch_bounds__(256) void qkv_tc(const float* __restrict__ x,
                                              const float* __restrict__ W,
                                              const float* __restrict__ bias) {
    __shared__ uint32_t Ah[QBM * QAST], Al[QBM * QAST];
    __shared__ uint32_t Bh[QBN * QBST], Bl[QBN * QBST];

    const int bm = blockIdx.x * QBM;
    const int bn = blockIdx.y * QBN;
    const int tid = threadIdx.x;
    const int w = tid >> 5;
    const int lane = tid & 31;
    const int ly = lane >> 2;
    const int lx = lane & 3;
    const int bln = tid & 63;   // B-load n
    const int blk = tid >> 6;   // B-load k-group (0..3), 8 k each

    float acc[8][4] = {};

    for (int k0 = 0; k0 < EMB; k0 += QBK) {
        __syncthreads();
        // A tile: 128 x 32 fp32 -> hi/lo bf16x2, row-major (k contiguous)
#pragma unroll
        for (int i = 0; i < 4; i++) {
            int f4 = tid + i * 256;
            int row = f4 >> 3;
            int c4 = f4 & 7;
            float4 v = *reinterpret_cast<const float4*>(
                x + (size_t)(bm + row) * EMB + k0 + c4 * 4);
            uint32_t h0, l0, h1, l1;
            split_pack(v.x, v.y, h0, l0);
            split_pack(v.z, v.w, h1, l1);
            Ah[row * QAST + 2 * c4 + 0] = h0;
            Al[row * QAST + 2 * c4 + 0] = l0;
            Ah[row * QAST + 2 * c4 + 1] = h1;
            Al[row * QAST + 2 * c4 + 1] = l1;
        }
        // B tile: 32 x 64 fp32, stored transposed [n][k] (coalesced k-grouped)
        {
            const float* wp = W + (size_t)(k0 + blk * 8) * H3 + bn + bln;
            float f[8];
#pragma unroll
            for (int j = 0; j < 8; j++) f[j] = wp[(size_t)j * H3];
#pragma unroll
            for (int jj = 0; jj < 4; jj++) {
                uint32_t h, l;
                split_pack(f[2 * jj], f[2 * jj + 1], h, l);
                Bh[bln * QBST + blk * 4 + jj] = h;
                Bl[bln * QBST + blk * 4 + jj] = l;
            }
        }
        __syncthreads();

#pragma unroll
        for (int ks = 0; ks < 2; ks++) {
            uint32_t ah[4], al[4];
            int ab = (w * 16 + ly) * QAST + ks * 8 + lx;
            ah[0] = Ah[ab];               al[0] = Al[ab];
            ah[1] = Ah[ab + 8 * QAST];    al[1] = Al[ab + 8 * QAST];
            ah[2] = Ah[ab + 4];           al[2] = Al[ab + 4];
            ah[3] = Ah[ab + 8 * QAST + 4];al[3] = Al[ab + 8 * QAST + 4];
#pragma unroll
            for (int nb = 0; nb < 8; nb++) {
                int bi = (nb * 8 + ly) * QBST + ks * 8 + lx;
                uint32_t bh0 = Bh[bi], bh1 = Bh[bi + 4];
                uint32_t bl0 = Bl[bi], bl1 = Bl[bi + 4];
                mma_bf16(acc[nb], ah, bh0, bh1);
                mma_bf16(acc[nb], ah, bl0, bl1);
                mma_bf16(acc[nb], al, bh0, bh1);
            }
        }
    }

    // Epilogue
    int r0 = bm + w * 16 + ly;
#pragma unroll
    for (int nb = 0; nb < 8; nb++) {
        int col = bn + nb * 8 + 2 * lx;
        float b0 = bias[col], b1 = bias[col + 1];
        *reinterpret_cast<float2*>(&g_qkv[(size_t)r0 * H3 + col]) =
            make_float2(acc[nb][0] + b0, acc[nb][1] + b1);
        *reinterpret_cast<float2*>(&g_qkv[(size_t)(r0 + 8) * H3 + col]) =
            make_float2(acc[nb][2] + b0, acc[nb][3] + b1);
    }
}

// ---------------------------------------------------------------------------
// Kernel 2: flash attention on tensor pipe (tf32 mma m16n8k8). Unchanged (R3).
// ---------------------------------------------------------------------------
#define BQ    128
#define BKV   64
#define SROW2 68
#define ATT_SMEM2 (256 * SROW2 * 4)

__global__ __launch_bounds__(256, 2) void attn_tc() {
    extern __shared__ float sm2[];
    float* sK  = sm2;                   // [64 kv][68]
    float* sVt = sm2 + 64 * SROW2;      // [64 d][68 kv]
    float* sP  = sm2 + 128 * SROW2;     // [128 q][68]

    const int b    = blockIdx.y;
    const int q0   = blockIdx.x * BQ;
    const int tid  = threadIdx.x;
    const int w    = tid >> 5;
    const int lane = tid & 31;
    const int ly   = lane >> 2;
    const int lx   = lane & 3;

    float* sPw = sP + w * 16 * SROW2;
    const float qscale = 0.125f * 1.44269504088896340736f;

    uint32_t Aq[8][4];
    {
        const float* qb = g_qkv + (size_t)(b * SEQ + q0 + w * 16) * H3;
#pragma unroll
        for (int ks = 0; ks < 8; ks++) {
            int c = ks * 8 + lx;
            Aq[ks][0] = f2tf32(qb[(size_t)(ly    ) * H3 + c    ] * qscale);
            Aq[ks][1] = f2tf32(qb[(size_t)(ly + 8) * H3 + c    ] * qscale);
            Aq[ks][2] = f2tf32(qb[(size_t)(ly    ) * H3 + c + 4] * qscale);
            Aq[ks][3] = f2tf32(qb[(size_t)(ly + 8) * H3 + c + 4] * qscale);
        }
    }

    float O[8][4];
    float mrow0 = -1e30f, mrow1 = -1e30f, lrow0 = 0.f, lrow1 = 0.f;
#pragma unroll
    for (int nb = 0; nb < 8; nb++)
#pragma unroll
        for (int j = 0; j < 4; j++) O[nb][j] = 0.f;

    for (int kv0 = 0; kv0 < SEQ; kv0 += BKV) {
        __syncthreads();
        {
            int c  = tid >> 2;
            int d0 = (tid & 3) * 16;
            const float* kp = g_qkv + (size_t)(b * SEQ + kv0 + c) * H3 + HEAD;
            const float* vp = kp + HEAD;
#pragma unroll
            for (int i = 0; i < 16; i += 4) {
                float4 k4 = *reinterpret_cast<const float4*>(kp + d0 + i);
                sK[c * SROW2 + d0 + i + 0] = __uint_as_float(f2tf32(k4.x));
                sK[c * SROW2 + d0 + i + 1] = __uint_as_float(f2tf32(k4.y));
                sK[c * SROW2 + d0 + i + 2] = __uint_as_float(f2tf32(k4.z));
                sK[c * SROW2 + d0 + i + 3] = __uint_as_float(f2tf32(k4.w));
                float4 v4 = *reinterpret_cast<const float4*>(vp + d0 + i);
                sVt[(d0 + i + 0) * SROW2 + c] = __uint_as_float(f2tf32(v4.x));
                sVt[(d0 + i + 1) * SROW2 + c] = __uint_as_float(f2tf32(v4.y));
                sVt[(d0 + i + 2) * SROW2 + c] = __uint_as_float(f2tf32(v4.z));
                sVt[(d0 + i + 3) * SROW2 + c] = __uint_as_float(f2tf32(v4.w));
            }
        }
        __syncthreads();

        float S[8][4];
#pragma unroll
        for (int nb = 0; nb < 8; nb++)
#pragma unroll
            for (int j = 0; j < 4; j++) S[nb][j] = 0.f;

#pragma unroll
        for (int ks = 0; ks < 8; ks++) {
#pragma unroll
            for (int nb = 0; nb < 8; nb++) {
                uint32_t b0 = __float_as_uint(sK[(nb * 8 + ly) * SROW2 + ks * 8 + lx]);
                uint32_t b1 = __float_as_uint(sK[(nb * 8 + ly) * SROW2 + ks * 8 + 4 + lx]);
                mma_tf32(S[nb], Aq[ks], b0, b1);
            }
        }

        float mt0 = -1e30f, mt1 = -1e30f;
#pragma unroll
        for (int nb = 0; nb < 8; nb++) {
            mt0 = fmaxf(mt0, fmaxf(S[nb][0], S[nb][1]));
            mt1 = fmaxf(mt1, fmaxf(S[nb][2], S[nb][3]));
        }
        mt0 = fmaxf(mt0, __shfl_xor_sync(0xffffffffu, mt0, 1));
        mt0 = fmaxf(mt0, __shfl_xor_sync(0xffffffffu, mt0, 2));
        mt1 = fmaxf(mt1, __shfl_xor_sync(0xffffffffu, mt1, 1));
        mt1 = fmaxf(mt1, __shfl_xor_sync(0xffffffffu, mt1, 2));

        float mn0 = fmaxf(mrow0, mt0);
        float mn1 = fmaxf(mrow1, mt1);
        float corr0 = exp2a(mrow0 - mn0);
        float corr1 = exp2a(mrow1 - mn1);

        float rs0 = 0.f, rs1 = 0.f;
#pragma unroll
        for (int nb = 0; nb < 8; nb++) {
            S[nb][0] = exp2a(S[nb][0] - mn0);
            S[nb][1] = exp2a(S[nb][1] - mn0);
            S[nb][2] = exp2a(S[nb][2] - mn1);
            S[nb][3] = exp2a(S[nb][3] - mn1);
            rs0 += S[nb][0] + S[nb][1];
            rs1 += S[nb][2] + S[nb][3];
        }
        rs0 += __shfl_xor_sync(0xffffffffu, rs0, 1);
        rs0 += __shfl_xor_sync(0xffffffffu, rs0, 2);
        rs1 += __shfl_xor_sync(0xffffffffu, rs1, 1);
        rs1 += __shfl_xor_sync(0xffffffffu, rs1, 2);

        lrow0 = lrow0 * corr0 + rs0;
        lrow1 = lrow1 * corr1 + rs1;
        mrow0 = mn0;
        mrow1 = mn1;

#pragma unroll
        for (int nb = 0; nb < 8; nb++) {
            O[nb][0] *= corr0;
            O[nb][1] *= corr0;
            O[nb][2] *= corr1;
            O[nb][3] *= corr1;
        }

#pragma unroll
        for (int nb = 0; nb < 8; nb++) {
            uint2 p01 = make_uint2(f2tf32(S[nb][0]), f2tf32(S[nb][1]));
            *reinterpret_cast<uint2*>(&sPw[ly * SROW2 + nb * 8 + 2 * lx]) = p01;
            uint2 p23 = make_uint2(f2tf32(S[nb][2]), f2tf32(S[nb][3]));
            *reinterpret_cast<uint2*>(&sPw[(ly + 8) * SROW2 + nb * 8 + 2 * lx]) = p23;
        }
        __syncwarp();

#pragma unroll
        for (int ks = 0; ks < 8; ks++) {
            uint32_t pa[4];
            pa[0] = __float_as_uint(sPw[(ly    ) * SROW2 + ks * 8 + lx]);
            pa[1] = __float_as_uint(sPw[(ly + 8) * SROW2 + ks * 8 + lx]);
            pa[2] = __float_as_uint(sPw[(ly    ) * SROW2 + ks * 8 + 4 + lx]);
            pa[3] = __float_as_uint(sPw[(ly + 8) * SROW2 + ks * 8 + 4 + lx]);
#pragma unroll
            for (int nb = 0; nb < 8; nb++) {
                uint32_t b0 = __float_as_uint(sVt[(nb * 8 + ly) * SROW2 + ks * 8 + lx]);
                uint32_t b1 = __float_as_uint(sVt[(nb * 8 + ly) * SROW2 + ks * 8 + 4 + lx]);
                mma_tf32(O[nb], pa, b0, b1);
            }
        }
    }

    float inv0 = 1.f / lrow0;
    float inv1 = 1.f / lrow1;
    int r0g = b * SEQ + q0 + w * 16 + ly;
#pragma unroll
    for (int nb = 0; nb < 8; nb++) {
        float2 v0 = make_float2(O[nb][0] * inv0, O[nb][1] * inv0);
        *reinterpret_cast<float2*>(&g_ctx[(size_t)r0g * HEAD + nb * 8 + 2 * lx]) = v0;
        float2 v1 = make_float2(O[nb][2] * inv1, O[nb][3] * inv1);
        *reinterpret_cast<float2*>(&g_ctx[(size_t)(r0g + 8) * HEAD + nb * 8 + 2 * lx]) = v1;
    }
}

// ---------------------------------------------------------------------------
// Kernel 3: output projection on tensor pipe (bf16 3-term split).
// out[16384,1024] = ctx[16384,64] * W_out[64,1024] + b. BM=128, BN=128, K=64.
// 8 warps, each warp: 16 rows x 128 cols (16 n-blocks).
// ---------------------------------------------------------------------------
#define OBM 128
#define OBN 128
#define OST 36   // uint stride (32 used); 36*ly%32 = 4*ly -> conflict-free LDS
#define OUT_SMEM (4 * 128 * OST * 4)  // Ah+Al+Bh+Bl = 73728 B

__global__ __launch_bounds__(256) void out_tc(const float* __restrict__ Wout,
                                              const float* __restrict__ bout,
                                              float* __restrict__ out) {
    extern __shared__ uint32_t osm[];
    uint32_t* Ah = osm;
    uint32_t* Al = Ah + OBM * OST;
    uint32_t* Bh = Al + OBM * OST;
    uint32_t* Bl = Bh + OBN * OST;

    const int bm = blockIdx.x * OBM;
    const int bn = blockIdx.y * OBN;
    const int tid = threadIdx.x;
    const int w = tid >> 5;
    const int lane = tid & 31;
    const int ly = lane >> 2;
    const int lx = lane & 3;

    // A tile: ctx 128 x 64 fp32 -> hi/lo, row-major
#pragma unroll
    for (int i = 0; i < 8; i++) {
        int f4 = tid + i * 256;
        int row = f4 >> 4;
        int c4 = f4 & 15;
        float4 v = *reinterpret_cast<const float4*>(
            g_ctx + (size_t)(bm + row) * HEAD + c4 * 4);
        uint32_t h0, l0, h1, l1;
        split_pack(v.x, v.y, h0, l0);
        split_pack(v.z, v.w, h1, l1);
        Ah[row * OST + 2 * c4 + 0] = h0;
        Al[row * OST + 2 * c4 + 0] = l0;
        Ah[row * OST + 2 * c4 + 1] = h1;
        Al[row * OST + 2 * c4 + 1] = l1;
    }
    // B tile: W_out 64 x 128 -> [n][k] hi/lo (coalesced k-grouped loads)
    {
        int n  = tid & 127;
        int kg = tid >> 7;   // 0..1, 32 k each
        const float* wp = Wout + (size_t)(kg * 32) * EMB + bn + n;
#pragma unroll
        for (int m = 0; m < 16; m++) {
            float f0 = wp[(size_t)(2 * m    ) * EMB];
            float f1 = wp[(size_t)(2 * m + 1) * EMB];
            uint32_t h, l;
            split_pack(f0, f1, h, l);
            Bh[n * OST + kg * 16 + m] = h;
            Bl[n * OST + kg * 16 + m] = l;
        }
    }
    __syncthreads();

    float acc[16][4] = {};
#pragma unroll
    for (int ks = 0; ks < 4; ks++) {
        uint32_t ah[4], al[4];
        int ab = (w * 16 + ly) * OST + ks * 8 + lx;
        ah[0] = Ah[ab];              al[0] = Al[ab];
        ah[1] = Ah[ab + 8 * OST];    al[1] = Al[ab + 8 * OST];
        ah[2] = Ah[ab + 4];          al[2] = Al[ab + 4];
        ah[3] = Ah[ab + 8 * OST + 4];al[3] = Al[ab + 8 * OST + 4];
#pragma unroll
        for (int nb = 0; nb < 16; nb++) {
            int bi = (nb * 8 + ly) * OST + ks * 8 + lx;
            uint32_t bh0 = Bh[bi], bh1 = Bh[bi + 4];
            uint32_t bl0 = Bl[bi], bl1 = Bl[bi + 4];
            mma_bf16(acc[nb], ah, bh0, bh1);
            mma_bf16(acc[nb], ah, bl0, bl1);
            mma_bf16(acc[nb], al, bh0, bh1);
        }
    }

    int r0 = bm + w * 16 + ly;
#pragma unroll
    for (int nb = 0; nb < 16; nb++) {
        int col = bn + nb * 8 + 2 * lx;
        float b0 = bout[col], b1 = bout[col + 1];
        *reinterpret_cast<float2*>(&out[(size_t)r0 * EMB + col]) =
            make_float2(acc[nb][0] + b0, acc[nb][1] + b1);
        *reinterpret_cast<float2*>(&out[(size_t)(r0 + 8) * EMB + col]) =
            make_float2(acc[nb][2] + b0, acc[nb][3] + b1);
    }
}

// ---------------------------------------------------------------------------
extern "C" void kernel_launch(void* const* d_in, const int* in_sizes, int n_in,
                              void* d_out, int out_size) {
    const float* x     = (const float*)d_in[0];
    const float* W_qkv = (const float*)d_in[1];
    const float* b_qkv = (const float*)d_in[2];
    const float* W_out = (const float*)d_in[3];
    const float* b_out = (const float*)d_in[4];
    float* out = (float*)d_out;

    qkv_tc<<<dim3(MTOT / QBM, H3 / QBN), 256>>>(x, W_qkv, b_qkv);

    cudaFuncSetAttribute(attn_tc, cudaFuncAttributeMaxDynamicSharedMemorySize, ATT_SMEM2);
    attn_tc<<<dim3(SEQ / BQ, BATCH), 256, ATT_SMEM2>>>();

    cudaFuncSetAttribute(out_tc, cudaFuncAttributeMaxDynamicSharedMemorySize, OUT_SMEM);
    out_tc<<<dim3(MTOT / OBM, EMB / OBN), 256, OUT_SMEM>>>(W_out, b_out, out);
}

// round 7
// speedup vs baseline: 2.9014x; 1.0748x over previous
#include <cuda_runtime.h>
#include <cuda_bf16.h>
#include <cstdint>

#define BATCH 4
#define SEQ   4096
#define EMB   1024
#define HEAD  64
#define H3    192
#define MTOT  (BATCH*SEQ)   // 16384

// Scratch (allocation-free rule: device globals)
__device__ __align__(16) float g_qkv[MTOT * H3];        // 12.6 MB
__device__ __align__(16) float g_ctx[MTOT * HEAD];      //  4.2 MB
__device__ __align__(16) float g_po[2][MTOT * HEAD];    //  8.4 MB partial O
__device__ __align__(16) float g_pm[2][MTOT];
__device__ __align__(16) float g_pl[2][MTOT];

// ---------------------------------------------------------------------------
// Helpers
// ---------------------------------------------------------------------------
__device__ __forceinline__ uint32_t f2tf32(float f) {
    uint32_t r;
    asm("cvt.rna.tf32.f32 %0, %1;" : "=r"(r) : "f"(f));
    return r;
}
__device__ __forceinline__ float exp2a(float x) {
    float y;
    asm("ex2.approx.f32 %0, %1;" : "=f"(y) : "f"(x));
    return y;
}
__device__ __forceinline__ void mma_tf32(float c[4], const uint32_t a[4],
                                         uint32_t b0, uint32_t b1) {
    asm volatile(
        "mma.sync.aligned.m16n8k8.row.col.f32.tf32.tf32.f32 "
        "{%0,%1,%2,%3}, {%4,%5,%6,%7}, {%8,%9}, {%0,%1,%2,%3};\n"
        : "+f"(c[0]), "+f"(c[1]), "+f"(c[2]), "+f"(c[3])
        : "r"(a[0]), "r"(a[1]), "r"(a[2]), "r"(a[3]), "r"(b0), "r"(b1));
}
__device__ __forceinline__ void mma_bf16(float c[4], const uint32_t a[4],
                                         uint32_t b0, uint32_t b1) {
    asm volatile(
        "mma.sync.aligned.m16n8k16.row.col.f32.bf16.bf16.f32 "
        "{%0,%1,%2,%3}, {%4,%5,%6,%7}, {%8,%9}, {%0,%1,%2,%3};\n"
        : "+f"(c[0]), "+f"(c[1]), "+f"(c[2]), "+f"(c[3])
        : "r"(a[0]), "r"(a[1]), "r"(a[2]), "r"(a[3]), "r"(b0), "r"(b1));
}
__device__ __forceinline__ void split_pack(float x, float y,
                                           uint32_t& hi, uint32_t& lo) {
    __nv_bfloat16 hx = __float2bfloat16_rn(x);
    __nv_bfloat16 hy = __float2bfloat16_rn(y);
    __nv_bfloat16 lxx = __float2bfloat16_rn(x - __bfloat162float(hx));
    __nv_bfloat16 lyy = __float2bfloat16_rn(y - __bfloat162float(hy));
    __nv_bfloat162 h2 = __halves2bfloat162(hx, hy);
    __nv_bfloat162 l2 = __halves2bfloat162(lxx, lyy);
    hi = *reinterpret_cast<uint32_t*>(&h2);
    lo = *reinterpret_cast<uint32_t*>(&l2);
}
__device__ __forceinline__ void ldsm_x4(uint32_t r[4], uint32_t addr) {
    asm volatile("ldmatrix.sync.aligned.m8n8.x4.shared.b16 {%0,%1,%2,%3}, [%4];"
                 : "=r"(r[0]), "=r"(r[1]), "=r"(r[2]), "=r"(r[3]) : "r"(addr));
}

// ---------------------------------------------------------------------------
// Kernel 1: QKV projection (bf16 3-term split). Inner loop reordered for ILP:
// B fragments cached in registers, 3 passes of 8 independent mma each.
// ---------------------------------------------------------------------------
#define QBM 128
#define QBN 64
#define QBK 32
#define QAST 20
#define QBST 20

__global__ __launch_bounds__(256) void qkv_tc(const float* __restrict__ x,
                                              const float* __restrict__ W,
                                              const float* __restrict__ bias) {
    __shared__ uint32_t Ah[QBM * QAST], Al[QBM * QAST];
    __shared__ uint32_t Bh[QBN * QBST], Bl[QBN * QBST];

    const int bm = blockIdx.x * QBM;
    const int bn = blockIdx.y * QBN;
    const int tid = threadIdx.x;
    const int w = tid >> 5;
    const int lane = tid & 31;
    const int ly = lane >> 2;
    const int lx = lane & 3;
    const int bln = tid & 63;
    const int blk = tid >> 6;

    float acc[8][4] = {};

    for (int k0 = 0; k0 < EMB; k0 += QBK) {
        __syncthreads();
#pragma unroll
        for (int i = 0; i < 4; i++) {
            int f4 = tid + i * 256;
            int row = f4 >> 3;
            int c4 = f4 & 7;
            float4 v = *reinterpret_cast<const float4*>(
                x + (size_t)(bm + row) * EMB + k0 + c4 * 4);
            uint32_t h0, l0, h1, l1;
            split_pack(v.x, v.y, h0, l0);
            split_pack(v.z, v.w, h1, l1);
            Ah[row * QAST + 2 * c4 + 0] = h0;
            Al[row * QAST + 2 * c4 + 0] = l0;
            Ah[row * QAST + 2 * c4 + 1] = h1;
            Al[row * QAST + 2 * c4 + 1] = l1;
        }
        {
            const float* wp = W + (size_t)(k0 + blk * 8) * H3 + bn + bln;
            float f[8];
#pragma unroll
            for (int j = 0; j < 8; j++) f[j] = wp[(size_t)j * H3];
#pragma unroll
            for (int jj = 0; jj < 4; jj++) {
                uint32_t h, l;
                split_pack(f[2 * jj], f[2 * jj + 1], h, l);
                Bh[bln * QBST + blk * 4 + jj] = h;
                Bl[bln * QBST + blk * 4 + jj] = l;
            }
        }
        __syncthreads();

#pragma unroll
        for (int ks = 0; ks < 2; ks++) {
            uint32_t ah[4], al[4];
            int ab = (w * 16 + ly) * QAST + ks * 8 + lx;
            ah[0] = Ah[ab];                al[0] = Al[ab];
            ah[1] = Ah[ab + 8 * QAST];     al[1] = Al[ab + 8 * QAST];
            ah[2] = Ah[ab + 4];            al[2] = Al[ab + 4];
            ah[3] = Ah[ab + 8 * QAST + 4]; al[3] = Al[ab + 8 * QAST + 4];
            uint32_t bh[8][2], bl[8][2];
#pragma unroll
            for (int nb = 0; nb < 8; nb++) {
                int bi = (nb * 8 + ly) * QBST + ks * 8 + lx;
                bh[nb][0] = Bh[bi]; bh[nb][1] = Bh[bi + 4];
                bl[nb][0] = Bl[bi]; bl[nb][1] = Bl[bi + 4];
            }
#pragma unroll
            for (int nb = 0; nb < 8; nb++) mma_bf16(acc[nb], ah, bh[nb][0], bh[nb][1]);
#pragma unroll
            for (int nb = 0; nb < 8; nb++) mma_bf16(acc[nb], ah, bl[nb][0], bl[nb][1]);
#pragma unroll
            for (int nb = 0; nb < 8; nb++) mma_bf16(acc[nb], al, bh[nb][0], bh[nb][1]);
        }
    }

    int r0 = bm + w * 16 + ly;
#pragma unroll
    for (int nb = 0; nb < 8; nb++) {
        int col = bn + nb * 8 + 2 * lx;
        float b0 = bias[col], b1 = bias[col + 1];
        *reinterpret_cast<float2*>(&g_qkv[(size_t)r0 * H3 + col]) =
            make_float2(acc[nb][0] + b0, acc[nb][1] + b1);
        *reinterpret_cast<float2*>(&g_qkv[(size_t)(r0 + 8) * H3 + col]) =
            make_float2(acc[nb][2] + b0, acc[nb][3] + b1);
    }
}

// ---------------------------------------------------------------------------
// Kernel 2: flash attention, split-KV (blockIdx.z = half), ldmatrix fragments.
// BQ=128 (8 warps x m16), KV tiles of 64, 32 tiles per block.
// Partial unnormalized O + (m,l) written to globals; combined by attn_combine.
// ---------------------------------------------------------------------------
#define BQ    128
#define BKV   64
#define SROW2 68
#define KVHALF (SEQ/2)
#define ATT_SMEM2 (256 * SROW2 * 4)

__global__ __launch_bounds__(256, 2) void attn_tc() {
    extern __shared__ float sm2[];
    float* sK  = sm2;                   // [64 kv][68 d]
    float* sVt = sm2 + 64 * SROW2;      // [64 d][68 kv]
    float* sP  = sm2 + 128 * SROW2;     // [128 q][68 kv] per-warp strips

    const int b    = blockIdx.y;
    const int q0   = blockIdx.x * BQ;
    const int z    = blockIdx.z;        // KV half
    const int tid  = threadIdx.x;
    const int w    = tid >> 5;
    const int lane = tid & 31;
    const int ly   = lane >> 2;
    const int lx   = lane & 3;
    const int mat  = lane >> 3;         // ldmatrix matrix index 0..3
    const int mr   = lane & 7;          // ldmatrix row within matrix

    float* sPw = sP + w * 16 * SROW2;
    const float qscale = 0.125f * 1.44269504088896340736f;

    // ldmatrix base addresses (bytes, shared space)
    const uint32_t aK = (uint32_t)__cvta_generic_to_shared(
        sK + ((mat >> 1) * 8 + mr) * SROW2 + (mat & 1) * 4);
    const uint32_t aV = (uint32_t)__cvta_generic_to_shared(
        sVt + ((mat >> 1) * 8 + mr) * SROW2 + (mat & 1) * 4);
    const uint32_t aP = (uint32_t)__cvta_generic_to_shared(
        sPw + ((mat & 1) * 8 + mr) * SROW2 + (mat >> 1) * 4);

    // Q fragments, register-resident tf32 (pre-scaled)
    uint32_t Aq[8][4];
    {
        const float* qb = g_qkv + (size_t)(b * SEQ + q0 + w * 16) * H3;
#pragma unroll
        for (int ks = 0; ks < 8; ks++) {
            int c = ks * 8 + lx;
            Aq[ks][0] = f2tf32(qb[(size_t)(ly    ) * H3 + c    ] * qscale);
            Aq[ks][1] = f2tf32(qb[(size_t)(ly + 8) * H3 + c    ] * qscale);
            Aq[ks][2] = f2tf32(qb[(size_t)(ly    ) * H3 + c + 4] * qscale);
            Aq[ks][3] = f2tf32(qb[(size_t)(ly + 8) * H3 + c + 4] * qscale);
        }
    }

    float O[8][4];
    float mrow0 = -1e30f, mrow1 = -1e30f, lrow0 = 0.f, lrow1 = 0.f;
#pragma unroll
    for (int nb = 0; nb < 8; nb++)
#pragma unroll
        for (int j = 0; j < 4; j++) O[nb][j] = 0.f;

    const int kv_beg = z * KVHALF;
    for (int kv0 = kv_beg; kv0 < kv_beg + KVHALF; kv0 += BKV) {
        __syncthreads();
        // stage K (vectorized tf32) and V (transposed, scalar)
        {
            int c  = tid >> 2;
            int d0 = (tid & 3) * 16;
            const float* kp = g_qkv + (size_t)(b * SEQ + kv0 + c) * H3 + HEAD;
            const float* vp = kp + HEAD;
#pragma unroll
            for (int i = 0; i < 16; i += 4) {
                float4 k4 = *reinterpret_cast<const float4*>(kp + d0 + i);
                uint4 kt;
                kt.x = f2tf32(k4.x); kt.y = f2tf32(k4.y);
                kt.z = f2tf32(k4.z); kt.w = f2tf32(k4.w);
                *reinterpret_cast<uint4*>(&sK[c * SROW2 + d0 + i]) = kt;
                float4 v4 = *reinterpret_cast<const float4*>(vp + d0 + i);
                sVt[(d0 + i + 0) * SROW2 + c] = __uint_as_float(f2tf32(v4.x));
                sVt[(d0 + i + 1) * SROW2 + c] = __uint_as_float(f2tf32(v4.y));
                sVt[(d0 + i + 2) * SROW2 + c] = __uint_as_float(f2tf32(v4.z));
                sVt[(d0 + i + 3) * SROW2 + c] = __uint_as_float(f2tf32(v4.w));
            }
        }
        __syncthreads();

        // S = Q K^T via ldmatrix B fragments (2 n-blocks per LDSM.x4)
        float S[8][4];
#pragma unroll
        for (int nb = 0; nb < 8; nb++)
#pragma unroll
            for (int j = 0; j < 4; j++) S[nb][j] = 0.f;

#pragma unroll
        for (int ks = 0; ks < 8; ks++) {
#pragma unroll
            for (int p = 0; p < 4; p++) {
                uint32_t bb[4];
                ldsm_x4(bb, aK + (uint32_t)((p * 16 * SROW2 + ks * 8) * 4));
                mma_tf32(S[2 * p    ], Aq[ks], bb[0], bb[1]);
                mma_tf32(S[2 * p + 1], Aq[ks], bb[2], bb[3]);
            }
        }

        // online softmax (base-2)
        float mt0 = -1e30f, mt1 = -1e30f;
#pragma unroll
        for (int nb = 0; nb < 8; nb++) {
            mt0 = fmaxf(mt0, fmaxf(S[nb][0], S[nb][1]));
            mt1 = fmaxf(mt1, fmaxf(S[nb][2], S[nb][3]));
        }
        mt0 = fmaxf(mt0, __shfl_xor_sync(0xffffffffu, mt0, 1));
        mt0 = fmaxf(mt0, __shfl_xor_sync(0xffffffffu, mt0, 2));
        mt1 = fmaxf(mt1, __shfl_xor_sync(0xffffffffu, mt1, 1));
        mt1 = fmaxf(mt1, __shfl_xor_sync(0xffffffffu, mt1, 2));

        float mn0 = fmaxf(mrow0, mt0);
        float mn1 = fmaxf(mrow1, mt1);
        float corr0 = exp2a(mrow0 - mn0);
        float corr1 = exp2a(mrow1 - mn1);

        float rs0 = 0.f, rs1 = 0.f;
#pragma unroll
        for (int nb = 0; nb < 8; nb++) {
            S[nb][0] = exp2a(S[nb][0] - mn0);
            S[nb][1] = exp2a(S[nb][1] - mn0);
            S[nb][2] = exp2a(S[nb][2] - mn1);
            S[nb][3] = exp2a(S[nb][3] - mn1);
            rs0 += S[nb][0] + S[nb][1];
            rs1 += S[nb][2] + S[nb][3];
        }
        rs0 += __shfl_xor_sync(0xffffffffu, rs0, 1);
        rs0 += __shfl_xor_sync(0xffffffffu, rs0, 2);
        rs1 += __shfl_xor_sync(0xffffffffu, rs1, 1);
        rs1 += __shfl_xor_sync(0xffffffffu, rs1, 2);

        lrow0 = lrow0 * corr0 + rs0;
        lrow1 = lrow1 * corr1 + rs1;
        mrow0 = mn0;
        mrow1 = mn1;

#pragma unroll
        for (int nb = 0; nb < 8; nb++) {
            O[nb][0] *= corr0;
            O[nb][1] *= corr0;
            O[nb][2] *= corr1;
            O[nb][3] *= corr1;
        }

        // write P (tf32) to per-warp strip
#pragma unroll
        for (int nb = 0; nb < 8; nb++) {
            uint2 p01 = make_uint2(f2tf32(S[nb][0]), f2tf32(S[nb][1]));
            *reinterpret_cast<uint2*>(&sPw[ly * SROW2 + nb * 8 + 2 * lx]) = p01;
            uint2 p23 = make_uint2(f2tf32(S[nb][2]), f2tf32(S[nb][3]));
            *reinterpret_cast<uint2*>(&sPw[(ly + 8) * SROW2 + nb * 8 + 2 * lx]) = p23;
        }
        __syncwarp();

        // O += P V via ldmatrix A and B fragments
#pragma unroll
        for (int ks = 0; ks < 8; ks++) {
            uint32_t pa[4];
            ldsm_x4(pa, aP + (uint32_t)(ks * 8 * 4));
#pragma unroll
            for (int p = 0; p < 4; p++) {
                uint32_t bb[4];
                ldsm_x4(bb, aV + (uint32_t)((p * 16 * SROW2 + ks * 8) * 4));
                mma_tf32(O[2 * p    ], pa, bb[0], bb[1]);
                mma_tf32(O[2 * p + 1], pa, bb[2], bb[3]);
            }
        }
    }

    // epilogue: store unnormalized partial O and (m, l)
    int r0g = b * SEQ + q0 + w * 16 + ly;
#pragma unroll
    for (int nb = 0; nb < 8; nb++) {
        *reinterpret_cast<float2*>(&g_po[z][(size_t)r0g * HEAD + nb * 8 + 2 * lx]) =
            make_float2(O[nb][0], O[nb][1]);
        *reinterpret_cast<float2*>(&g_po[z][(size_t)(r0g + 8) * HEAD + nb * 8 + 2 * lx]) =
            make_float2(O[nb][2], O[nb][3]);
    }
    if (lx == 0) {
        g_pm[z][r0g] = mrow0;      g_pl[z][r0g] = lrow0;
        g_pm[z][r0g + 8] = mrow1;  g_pl[z][r0g + 8] = lrow1;
    }
}

// Combine the two KV halves: ctx = (w0*O0 + w1*O1) / (w0*l0 + w1*l1)
__global__ __launch_bounds__(256) void attn_combine() {
    int idx = blockIdx.x * 256 + threadIdx.x;   // over MTOT*16 float4 units
    int row = idx >> 4;
    int c4 = (idx & 15) * 4;
    float m0 = g_pm[0][row], m1 = g_pm[1][row];
    float m = fmaxf(m0, m1);
    float w0 = exp2a(m0 - m), w1 = exp2a(m1 - m);
    float inv = 1.f / (w0 * g_pl[0][row] + w1 * g_pl[1][row]);
    float4 a = *reinterpret_cast<const float4*>(&g_po[0][(size_t)row * HEAD + c4]);
    float4 bb = *reinterpret_cast<const float4*>(&g_po[1][(size_t)row * HEAD + c4]);
    float4 r;
    r.x = (w0 * a.x + w1 * bb.x) * inv;
    r.y = (w0 * a.y + w1 * bb.y) * inv;
    r.z = (w0 * a.z + w1 * bb.z) * inv;
    r.w = (w0 * a.w + w1 * bb.w) * inv;
    *reinterpret_cast<float4*>(&g_ctx[(size_t)row * HEAD + c4]) = r;
}

// ---------------------------------------------------------------------------
// Kernel 3: output projection (bf16 3-term split), ILP-reordered.
// ---------------------------------------------------------------------------
#define OBM 128
#define OBN 128
#define OST 36
#define OUT_SMEM (4 * 128 * OST * 4)

__global__ __launch_bounds__(256) void out_tc(const float* __restrict__ Wout,
                                              const float* __restrict__ bout,
                                              float* __restrict__ out) {
    extern __shared__ uint32_t osm[];
    uint32_t* Ah = osm;
    uint32_t* Al = Ah + OBM * OST;
    uint32_t* Bh = Al + OBM * OST;
    uint32_t* Bl = Bh + OBN * OST;

    const int bm = blockIdx.x * OBM;
    const int bn = blockIdx.y * OBN;
    const int tid = threadIdx.x;
    const int w = tid >> 5;
    const int lane = tid & 31;
    const int ly = lane >> 2;
    const int lx = lane & 3;

#pragma unroll
    for (int i = 0; i < 8; i++) {
        int f4 = tid + i * 256;
        int row = f4 >> 4;
        int c4 = f4 & 15;
        float4 v = *reinterpret_cast<const float4*>(
            g_ctx + (size_t)(bm + row) * HEAD + c4 * 4);
        uint32_t h0, l0, h1, l1;
        split_pack(v.x, v.y, h0, l0);
        split_pack(v.z, v.w, h1, l1);
        Ah[row * OST + 2 * c4 + 0] = h0;
        Al[row * OST + 2 * c4 + 0] = l0;
        Ah[row * OST + 2 * c4 + 1] = h1;
        Al[row * OST + 2 * c4 + 1] = l1;
    }
    {
        int n  = tid & 127;
        int kg = tid >> 7;
        const float* wp = Wout + (size_t)(kg * 32) * EMB + bn + n;
#pragma unroll
        for (int m = 0; m < 16; m++) {
            float f0 = wp[(size_t)(2 * m    ) * EMB];
            float f1 = wp[(size_t)(2 * m + 1) * EMB];
            uint32_t h, l;
            split_pack(f0, f1, h, l);
            Bh[n * OST + kg * 16 + m] = h;
            Bl[n * OST + kg * 16 + m] = l;
        }
    }
    __syncthreads();

    float acc[16][4] = {};
#pragma unroll
    for (int ks = 0; ks < 4; ks++) {
        uint32_t ah[4], al[4];
        int ab = (w * 16 + ly) * OST + ks * 8 + lx;
        ah[0] = Ah[ab];               al[0] = Al[ab];
        ah[1] = Ah[ab + 8 * OST];     al[1] = Al[ab + 8 * OST];
        ah[2] = Ah[ab + 4];           al[2] = Al[ab + 4];
        ah[3] = Ah[ab + 8 * OST + 4]; al[3] = Al[ab + 8 * OST + 4];
#pragma unroll
        for (int h = 0; h < 2; h++) {
            uint32_t bh[8][2], bl[8][2];
#pragma unroll
            for (int j = 0; j < 8; j++) {
                int nb = h * 8 + j;
                int bi = (nb * 8 + ly) * OST + ks * 8 + lx;
                bh[j][0] = Bh[bi]; bh[j][1] = Bh[bi + 4];
                bl[j][0] = Bl[bi]; bl[j][1] = Bl[bi + 4];
            }
#pragma unroll
            for (int j = 0; j < 8; j++) mma_bf16(acc[h * 8 + j], ah, bh[j][0], bh[j][1]);
#pragma unroll
            for (int j = 0; j < 8; j++) mma_bf16(acc[h * 8 + j], ah, bl[j][0], bl[j][1]);
#pragma unroll
            for (int j = 0; j < 8; j++) mma_bf16(acc[h * 8 + j], al, bh[j][0], bh[j][1]);
        }
    }

    int r0 = bm + w * 16 + ly;
#pragma unroll
    for (int nb = 0; nb < 16; nb++) {
        int col = bn + nb * 8 + 2 * lx;
        float b0 = bout[col], b1 = bout[col + 1];
        *reinterpret_cast<float2*>(&out[(size_t)r0 * EMB + col]) =
            make_float2(acc[nb][0] + b0, acc[nb][1] + b1);
        *reinterpret_cast<float2*>(&out[(size_t)(r0 + 8) * EMB + col]) =
            make_float2(acc[nb][2] + b0, acc[nb][3] + b1);
    }
}

// ---------------------------------------------------------------------------
extern "C" void kernel_launch(void* const* d_in, const int* in_sizes, int n_in,
                              void* d_out, int out_size) {
    const float* x     = (const float*)d_in[0];
    const float* W_qkv = (const float*)d_in[1];
    const float* b_qkv = (const float*)d_in[2];
    const float* W_out = (const float*)d_in[3];
    const float* b_out = (const float*)d_in[4];
    float* out = (float*)d_out;

    qkv_tc<<<dim3(MTOT / QBM, H3 / QBN), 256>>>(x, W_qkv, b_qkv);

    cudaFuncSetAttribute(attn_tc, cudaFuncAttributeMaxDynamicSharedMemorySize, ATT_SMEM2);
    attn_tc<<<dim3(SEQ / BQ, BATCH, 2), 256, ATT_SMEM2>>>();
    attn_combine<<<MTOT * 16 / 256, 256>>>();

    cudaFuncSetAttribute(out_tc, cudaFuncAttributeMaxDynamicSharedMemorySize, OUT_SMEM);
    out_tc<<<dim3(MTOT / OBM, EMB / OBN), 256, OUT_SMEM>>>(W_out, b_out, out);
}

// round 9
// speedup vs baseline: 4.1312x; 1.4239x over previous
#include <cuda_runtime.h>
#include <cuda_fp16.h>
#include <cuda_bf16.h>
#include <cstdint>

#define BATCH 4
#define SEQ   4096
#define EMB   1024
#define HEAD  64
#define H3    192
#define MTOT  (BATCH*SEQ)   // 16384

// Scratch (allocation-free rule: device globals)
__device__ __align__(16) __half g_q16[MTOT * HEAD];   // 2 MB each, q pre-scaled
__device__ __align__(16) __half g_k16[MTOT * HEAD];
__device__ __align__(16) __half g_v16[MTOT * HEAD];
__device__ __align__(16) float  g_po[2][MTOT * HEAD]; // partial O (unnormalized)
__device__ __align__(16) float  g_pm[2][MTOT];
__device__ __align__(16) float  g_pl[2][MTOT];

// ---------------------------------------------------------------------------
// Helpers
// ---------------------------------------------------------------------------
__device__ __forceinline__ float exp2a(float x) {
    float y;
    asm("ex2.approx.f32 %0, %1;" : "=f"(y) : "f"(x));
    return y;
}
__device__ __forceinline__ void mma_bf16(float c[4], const uint32_t a[4],
                                         uint32_t b0, uint32_t b1) {
    asm volatile(
        "mma.sync.aligned.m16n8k16.row.col.f32.bf16.bf16.f32 "
        "{%0,%1,%2,%3}, {%4,%5,%6,%7}, {%8,%9}, {%0,%1,%2,%3};\n"
        : "+f"(c[0]), "+f"(c[1]), "+f"(c[2]), "+f"(c[3])
        : "r"(a[0]), "r"(a[1]), "r"(a[2]), "r"(a[3]), "r"(b0), "r"(b1));
}
__device__ __forceinline__ void mma_f16(float c[4], const uint32_t a[4],
                                        uint32_t b0, uint32_t b1) {
    asm volatile(
        "mma.sync.aligned.m16n8k16.row.col.f32.f16.f16.f32 "
        "{%0,%1,%2,%3}, {%4,%5,%6,%7}, {%8,%9}, {%0,%1,%2,%3};\n"
        : "+f"(c[0]), "+f"(c[1]), "+f"(c[2]), "+f"(c[3])
        : "r"(a[0]), "r"(a[1]), "r"(a[2]), "r"(a[3]), "r"(b0), "r"(b1));
}
__device__ __forceinline__ void split_pack(float x, float y,
                                           uint32_t& hi, uint32_t& lo) {
    __nv_bfloat16 hx = __float2bfloat16_rn(x);
    __nv_bfloat16 hy = __float2bfloat16_rn(y);
    __nv_bfloat16 lxx = __float2bfloat16_rn(x - __bfloat162float(hx));
    __nv_bfloat16 lyy = __float2bfloat16_rn(y - __bfloat162float(hy));
    __nv_bfloat162 h2 = __halves2bfloat162(hx, hy);
    __nv_bfloat162 l2 = __halves2bfloat162(lxx, lyy);
    hi = *reinterpret_cast<uint32_t*>(&h2);
    lo = *reinterpret_cast<uint32_t*>(&l2);
}
__device__ __forceinline__ void ldsm_x4(uint32_t r[4], uint32_t addr) {
    asm volatile("ldmatrix.sync.aligned.m8n8.x4.shared.b16 {%0,%1,%2,%3}, [%4];"
                 : "=r"(r[0]), "=r"(r[1]), "=r"(r[2]), "=r"(r[3]) : "r"(addr));
}
__device__ __forceinline__ void ldsm_x4t(uint32_t r[4], uint32_t addr) {
    asm volatile("ldmatrix.sync.aligned.m8n8.x4.trans.shared.b16 {%0,%1,%2,%3}, [%4];"
                 : "=r"(r[0]), "=r"(r[1]), "=r"(r[2]), "=r"(r[3]) : "r"(addr));
}
__device__ __forceinline__ void cp16(uint32_t dst, const void* src) {
    asm volatile("cp.async.cg.shared.global [%0], [%1], 16;" :: "r"(dst), "l"(src));
}

#define QSCALE (0.125f * 1.44269504088896340736f)   // (1/sqrt(64)) * log2(e)

// ---------------------------------------------------------------------------
// Kernel 1: QKV projection (bf16 3-term split) with register prefetch of the
// next k-tile. Epilogue writes fp16 q (pre-scaled) / k / v per blockIdx.y.
// ---------------------------------------------------------------------------
#define QBM 128
#define QBN 64
#define QBK 32
#define QAST 20
#define QBST 20

__global__ __launch_bounds__(256) void qkv_tc(const float* __restrict__ x,
                                              const float* __restrict__ W,
                                              const float* __restrict__ bias) {
    __shared__ uint32_t Ah[QBM * QAST], Al[QBM * QAST];
    __shared__ uint32_t Bh[QBN * QBST], Bl[QBN * QBST];

    const int bm = blockIdx.x * QBM;
    const int bn = blockIdx.y * QBN;   // 0=q, 64=k, 128=v
    const int tid = threadIdx.x;
    const int w = tid >> 5;
    const int lane = tid & 31;
    const int ly = lane >> 2;
    const int lx = lane & 3;
    const int bln = tid & 63;
    const int blk = tid >> 6;

    float acc[8][4] = {};

    // prefetch registers
    float4 ra[4];
    float rb[8];
#pragma unroll
    for (int i = 0; i < 4; i++) {
        int f4 = tid + i * 256;
        ra[i] = *reinterpret_cast<const float4*>(
            x + (size_t)(bm + (f4 >> 3)) * EMB + 0 + (f4 & 7) * 4);
    }
    {
        const float* wp = W + (size_t)(0 + blk * 8) * H3 + bn + bln;
#pragma unroll
        for (int j = 0; j < 8; j++) rb[j] = wp[(size_t)j * H3];
    }

    for (int k0 = 0; k0 < EMB; k0 += QBK) {
        // store staged regs -> smem (split to bf16 hi/lo)
#pragma unroll
        for (int i = 0; i < 4; i++) {
            int f4 = tid + i * 256;
            int row = f4 >> 3;
            int c4 = f4 & 7;
            uint32_t h0, l0, h1, l1;
            split_pack(ra[i].x, ra[i].y, h0, l0);
            split_pack(ra[i].z, ra[i].w, h1, l1);
            Ah[row * QAST + 2 * c4 + 0] = h0;
            Al[row * QAST + 2 * c4 + 0] = l0;
            Ah[row * QAST + 2 * c4 + 1] = h1;
            Al[row * QAST + 2 * c4 + 1] = l1;
        }
#pragma unroll
        for (int jj = 0; jj < 4; jj++) {
            uint32_t h, l;
            split_pack(rb[2 * jj], rb[2 * jj + 1], h, l);
            Bh[bln * QBST + blk * 4 + jj] = h;
            Bl[bln * QBST + blk * 4 + jj] = l;
        }
        __syncthreads();

        // issue next tile's loads (overlap with mma below)
        if (k0 + QBK < EMB) {
#pragma unroll
            for (int i = 0; i < 4; i++) {
                int f4 = tid + i * 256;
                ra[i] = *reinterpret_cast<const float4*>(
                    x + (size_t)(bm + (f4 >> 3)) * EMB + (k0 + QBK) + (f4 & 7) * 4);
            }
            const float* wp = W + (size_t)(k0 + QBK + blk * 8) * H3 + bn + bln;
#pragma unroll
            for (int j = 0; j < 8; j++) rb[j] = wp[(size_t)j * H3];
        }

#pragma unroll
        for (int ks = 0; ks < 2; ks++) {
            uint32_t ah[4], al[4];
            int ab = (w * 16 + ly) * QAST + ks * 8 + lx;
            ah[0] = Ah[ab];                al[0] = Al[ab];
            ah[1] = Ah[ab + 8 * QAST];     al[1] = Al[ab + 8 * QAST];
            ah[2] = Ah[ab + 4];            al[2] = Al[ab + 4];
            ah[3] = Ah[ab + 8 * QAST + 4]; al[3] = Al[ab + 8 * QAST + 4];
            uint32_t bh[8][2], bl[8][2];
#pragma unroll
            for (int nb = 0; nb < 8; nb++) {
                int bi = (nb * 8 + ly) * QBST + ks * 8 + lx;
                bh[nb][0] = Bh[bi]; bh[nb][1] = Bh[bi + 4];
                bl[nb][0] = Bl[bi]; bl[nb][1] = Bl[bi + 4];
            }
#pragma unroll
            for (int nb = 0; nb < 8; nb++) mma_bf16(acc[nb], ah, bh[nb][0], bh[nb][1]);
#pragma unroll
            for (int nb = 0; nb < 8; nb++) mma_bf16(acc[nb], ah, bl[nb][0], bl[nb][1]);
#pragma unroll
            for (int nb = 0; nb < 8; nb++) mma_bf16(acc[nb], al, bh[nb][0], bh[nb][1]);
        }
        __syncthreads();
    }

    // epilogue: fp16 outputs (q pre-scaled)
    __half* dst = (blockIdx.y == 0) ? g_q16 : (blockIdx.y == 1) ? g_k16 : g_v16;
    const float sc = (blockIdx.y == 0) ? QSCALE : 1.0f;
    int r0 = bm + w * 16 + ly;
#pragma unroll
    for (int nb = 0; nb < 8; nb++) {
        int col = nb * 8 + 2 * lx;
        float b0 = bias[bn + col], b1 = bias[bn + col + 1];
        __half2 h0 = __floats2half2_rn((acc[nb][0] + b0) * sc, (acc[nb][1] + b1) * sc);
        __half2 h1 = __floats2half2_rn((acc[nb][2] + b0) * sc, (acc[nb][3] + b1) * sc);
        *reinterpret_cast<__half2*>(&dst[(size_t)r0 * HEAD + col]) = h0;
        *reinterpret_cast<__half2*>(&dst[(size_t)(r0 + 8) * HEAD + col]) = h1;
    }
}

// ---------------------------------------------------------------------------
// Kernel 2: fp16 flash attention, split-KV (z), cp.async double-buffered K/V,
// ldmatrix for all fragments (trans for V). BQ=128, KV tiles of 64.
// ---------------------------------------------------------------------------
#define BQ     128
#define PSTR   72                    // halves per row (144 B): LDSM conflict-free
#define KVHALF (SEQ / 2)
#define NTILE  (KVHALF / 64)
#define ATT_SMEM (4 * 64 * PSTR * 2 + 128 * PSTR * 2)   // 55296 B

__global__ __launch_bounds__(256, 2) void attn_fp16() {
    extern __shared__ __half smh[];
    __half* sPQ = smh + 4 * 64 * PSTR;   // [128][72] : Q staging, then P strips

    const int b    = blockIdx.y;
    const int q0   = blockIdx.x * BQ;
    const int z    = blockIdx.z;
    const int tid  = threadIdx.x;
    const int w    = tid >> 5;
    const int lane = tid & 31;
    const int ly   = lane >> 2;
    const int lx   = lane & 3;

    __half* sPw = sPQ + w * 16 * PSTR;

    const uint32_t smb = (uint32_t)__cvta_generic_to_shared(smh);
    const uint32_t bK  = smb;                       // [2][64][144B]
    const uint32_t bV  = smb + 2 * 64 * 144;
    const uint32_t bPQ = smb + 4 * 64 * 144;

    // staging assignment: 4 threads per row, 2 x 16B chunks each
    const int srow = tid >> 2;
    const int sc   = (tid & 3) * 2;
    const uint32_t dK0 = bK + srow * 144 + sc * 16;
    const uint32_t dV0 = bV + srow * 144 + sc * 16;
    const size_t gb = (size_t)b * SEQ * HEAD;
    const int kv_beg = z * KVHALF;

    // prologue: prefetch tile 0 into stage 0
    {
        const __half* ks = g_k16 + gb + (size_t)(kv_beg + srow) * HEAD + sc * 8;
        const __half* vs = g_v16 + gb + (size_t)(kv_beg + srow) * HEAD + sc * 8;
        cp16(dK0, ks); cp16(dK0 + 16, ks + 8);
        cp16(dV0, vs); cp16(dV0 + 16, vs + 8);
        asm volatile("cp.async.commit_group;");
    }

    // stage Q (overlaps with tile-0 cp.async)
#pragma unroll
    for (int i = 0; i < 4; i++) {
        int idx = tid + i * 256;
        int row = idx >> 3, c = idx & 7;
        uint4 v = *reinterpret_cast<const uint4*>(
            g_q16 + gb + (size_t)(q0 + row) * HEAD + c * 8);
        *reinterpret_cast<uint4*>(
            reinterpret_cast<char*>(sPQ) + row * 144 + c * 16) = v;
    }
    __syncthreads();

    // Q fragments (pre-scaled fp16), 4 k-steps
    uint32_t Aq[4][4];
    {
        const int qr = (lane & 7) + ((lane >> 3) & 1) * 8;
        const int qc = lane >> 4;
        uint32_t aQ = bPQ + (w * 16 + qr) * 144 + qc * 16;
#pragma unroll
        for (int ks = 0; ks < 4; ks++) ldsm_x4(Aq[ks], aQ + ks * 32);
    }

    float O[8][4];
    float mrow0 = -1e30f, mrow1 = -1e30f, lrow0 = 0.f, lrow1 = 0.f;
#pragma unroll
    for (int nb = 0; nb < 8; nb++)
#pragma unroll
        for (int j = 0; j < 4; j++) O[nb][j] = 0.f;

    // fragment address bases
    const int krB = ((lane >> 4) & 1) * 8 + (lane & 7);  // K B-frag row (n)
    const int kcB = (lane >> 3) & 1;                     // K chunk
    const int vr  = lane & 15, vc = lane >> 4;           // V trans rows/chunk
    const int pr  = (lane & 7) + ((lane >> 3) & 1) * 8;  // P A-frag row
    const uint32_t aP = bPQ + (w * 16 + pr) * 144 + (lane >> 4) * 16;

    for (int t = 0; t < NTILE; t++) {
        const int s = t & 1;
        if (t + 1 < NTILE) {
            const uint32_t off = ((t + 1) & 1) * 64 * 144;
            const __half* ks = g_k16 + gb + (size_t)(kv_beg + (t + 1) * 64 + srow) * HEAD + sc * 8;
            const __half* vs = g_v16 + gb + (size_t)(kv_beg + (t + 1) * 64 + srow) * HEAD + sc * 8;
            cp16(dK0 + off, ks); cp16(dK0 + off + 16, ks + 8);
            cp16(dV0 + off, vs); cp16(dV0 + off + 16, vs + 8);
            asm volatile("cp.async.commit_group;");
            asm volatile("cp.async.wait_group 1;");
        } else {
            asm volatile("cp.async.wait_group 0;");
        }
        __syncthreads();

        // --- S = Q K^T ---
        const uint32_t aK = bK + s * 64 * 144 + krB * 144 + kcB * 16;
        float S[8][4];
#pragma unroll
        for (int nb = 0; nb < 8; nb++)
#pragma unroll
            for (int j = 0; j < 4; j++) S[nb][j] = 0.f;
#pragma unroll
        for (int ks = 0; ks < 4; ks++)
#pragma unroll
            for (int p = 0; p < 4; p++) {
                uint32_t bb[4];
                ldsm_x4(bb, aK + p * 2304 + ks * 32);
                mma_f16(S[2 * p    ], Aq[ks], bb[0], bb[1]);
                mma_f16(S[2 * p + 1], Aq[ks], bb[2], bb[3]);
            }

        // --- online softmax (base-2, scale already folded into Q) ---
        float mt0 = -1e30f, mt1 = -1e30f;
#pragma unroll
        for (int nb = 0; nb < 8; nb++) {
            mt0 = fmaxf(mt0, fmaxf(S[nb][0], S[nb][1]));
            mt1 = fmaxf(mt1, fmaxf(S[nb][2], S[nb][3]));
        }
        mt0 = fmaxf(mt0, __shfl_xor_sync(0xffffffffu, mt0, 1));
        mt0 = fmaxf(mt0, __shfl_xor_sync(0xffffffffu, mt0, 2));
        mt1 = fmaxf(mt1, __shfl_xor_sync(0xffffffffu, mt1, 1));
        mt1 = fmaxf(mt1, __shfl_xor_sync(0xffffffffu, mt1, 2));

        float mn0 = fmaxf(mrow0, mt0);
        float mn1 = fmaxf(mrow1, mt1);
        float corr0 = exp2a(mrow0 - mn0);
        float corr1 = exp2a(mrow1 - mn1);

        float rs0 = 0.f, rs1 = 0.f;
#pragma unroll
        for (int nb = 0; nb < 8; nb++) {
            S[nb][0] = exp2a(S[nb][0] - mn0);
            S[nb][1] = exp2a(S[nb][1] - mn0);
            S[nb][2] = exp2a(S[nb][2] - mn1);
            S[nb][3] = exp2a(S[nb][3] - mn1);
            rs0 += S[nb][0] + S[nb][1];
            rs1 += S[nb][2] + S[nb][3];
        }
        rs0 += __shfl_xor_sync(0xffffffffu, rs0, 1);
        rs0 += __shfl_xor_sync(0xffffffffu, rs0, 2);
        rs1 += __shfl_xor_sync(0xffffffffu, rs1, 1);
        rs1 += __shfl_xor_sync(0xffffffffu, rs1, 2);

        lrow0 = lrow0 * corr0 + rs0;
        lrow1 = lrow1 * corr1 + rs1;
        mrow0 = mn0;
        mrow1 = mn1;

#pragma unroll
        for (int nb = 0; nb < 8; nb++) {
            O[nb][0] *= corr0;
            O[nb][1] *= corr0;
            O[nb][2] *= corr1;
            O[nb][3] *= corr1;
        }

        // --- P -> smem (fp16x2) ---
#pragma unroll
        for (int nb = 0; nb < 8; nb++) {
            *reinterpret_cast<__half2*>(&sPw[ly * PSTR + nb * 8 + 2 * lx]) =
                __floats2half2_rn(S[nb][0], S[nb][1]);
            *reinterpret_cast<__half2*>(&sPw[(ly + 8) * PSTR + nb * 8 + 2 * lx]) =
                __floats2half2_rn(S[nb][2], S[nb][3]);
        }
        __syncwarp();

        // --- O += P V  (V via ldmatrix.trans, stays row-major) ---
        const uint32_t aV = bV + s * 64 * 144 + vr * 144 + vc * 16;
#pragma unroll
        for (int ks = 0; ks < 4; ks++) {
            uint32_t pa[4];
            ldsm_x4(pa, aP + ks * 32);
#pragma unroll
            for (int p = 0; p < 4; p++) {
                uint32_t bb[4];
                ldsm_x4t(bb, aV + ks * 2304 + p * 32);
                mma_f16(O[2 * p    ], pa, bb[0], bb[1]);
                mma_f16(O[2 * p + 1], pa, bb[2], bb[3]);
            }
        }
        __syncthreads();
    }

    // epilogue: partial unnormalized O + (m, l)
    int r0g = b * SEQ + q0 + w * 16 + ly;
#pragma unroll
    for (int nb = 0; nb < 8; nb++) {
        *reinterpret_cast<float2*>(&g_po[z][(size_t)r0g * HEAD + nb * 8 + 2 * lx]) =
            make_float2(O[nb][0], O[nb][1]);
        *reinterpret_cast<float2*>(&g_po[z][(size_t)(r0g + 8) * HEAD + nb * 8 + 2 * lx]) =
            make_float2(O[nb][2], O[nb][3]);
    }
    if (lx == 0) {
        g_pm[z][r0g] = mrow0;      g_pl[z][r0g] = lrow0;
        g_pm[z][r0g + 8] = mrow1;  g_pl[z][r0g + 8] = lrow1;
    }
}

// ---------------------------------------------------------------------------
// Kernel 3: output projection (bf16 3-term split) with fused split-KV combine
// in the A-tile staging. out = combine(po0,po1) @ W_out + b.
// ---------------------------------------------------------------------------
#define OBM 128
#define OBN 128
#define OST 36
#define OUT_SMEM (4 * 128 * OST * 4)

__global__ __launch_bounds__(256) void out_tc(const float* __restrict__ Wout,
                                              const float* __restrict__ bout,
                                              float* __restrict__ out) {
    extern __shared__ uint32_t osm[];
    uint32_t* Ah = osm;
    uint32_t* Al = Ah + OBM * OST;
    uint32_t* Bh = Al + OBM * OST;
    uint32_t* Bl = Bh + OBN * OST;

    const int bm = blockIdx.x * OBM;
    const int bn = blockIdx.y * OBN;
    const int tid = threadIdx.x;
    const int w = tid >> 5;
    const int lane = tid & 31;
    const int ly = lane >> 2;
    const int lx = lane & 3;

    // A tile: combine partial O halves on the fly, split to bf16 hi/lo
#pragma unroll
    for (int i = 0; i < 8; i++) {
        int f4 = tid + i * 256;
        int row = f4 >> 4;
        int c4 = f4 & 15;
        int rg = bm + row;
        float m0 = g_pm[0][rg], m1 = g_pm[1][rg];
        float mx = fmaxf(m0, m1);
        float w0 = exp2a(m0 - mx), w1 = exp2a(m1 - mx);
        float inv = 1.f / (w0 * g_pl[0][rg] + w1 * g_pl[1][rg]);
        float4 a = *reinterpret_cast<const float4*>(&g_po[0][(size_t)rg * HEAD + c4 * 4]);
        float4 c = *reinterpret_cast<const float4*>(&g_po[1][(size_t)rg * HEAD + c4 * 4]);
        float vx = (w0 * a.x + w1 * c.x) * inv;
        float vy = (w0 * a.y + w1 * c.y) * inv;
        float vz = (w0 * a.z + w1 * c.z) * inv;
        float vw = (w0 * a.w + w1 * c.w) * inv;
        uint32_t h0, l0, h1, l1;
        split_pack(vx, vy, h0, l0);
        split_pack(vz, vw, h1, l1);
        Ah[row * OST + 2 * c4 + 0] = h0;
        Al[row * OST + 2 * c4 + 0] = l0;
        Ah[row * OST + 2 * c4 + 1] = h1;
        Al[row * OST + 2 * c4 + 1] = l1;
    }
    {
        int n  = tid & 127;
        int kg = tid >> 7;
        const float* wp = Wout + (size_t)(kg * 32) * EMB + bn + n;
#pragma unroll
        for (int m = 0; m < 16; m++) {
            float f0 = wp[(size_t)(2 * m    ) * EMB];
            float f1 = wp[(size_t)(2 * m + 1) * EMB];
            uint32_t h, l;
            split_pack(f0, f1, h, l);
            Bh[n * OST + kg * 16 + m] = h;
            Bl[n * OST + kg * 16 + m] = l;
        }
    }
    __syncthreads();

    float acc[16][4] = {};
#pragma unroll
    for (int ks = 0; ks < 4; ks++) {
        uint32_t ah[4], al[4];
        int ab = (w * 16 + ly) * OST + ks * 8 + lx;
        ah[0] = Ah[ab];               al[0] = Al[ab];
        ah[1] = Ah[ab + 8 * OST];     al[1] = Al[ab + 8 * OST];
        ah[2] = Ah[ab + 4];           al[2] = Al[ab + 4];
        ah[3] = Ah[ab + 8 * OST + 4]; al[3] = Al[ab + 8 * OST + 4];
#pragma unroll
        for (int h = 0; h < 2; h++) {
            uint32_t bh[8][2], bl[8][2];
#pragma unroll
            for (int j = 0; j < 8; j++) {
                int nb = h * 8 + j;
                int bi = (nb * 8 + ly) * OST + ks * 8 + lx;
                bh[j][0] = Bh[bi]; bh[j][1] = Bh[bi + 4];
                bl[j][0] = Bl[bi]; bl[j][1] = Bl[bi + 4];
            }
#pragma unroll
            for (int j = 0; j < 8; j++) mma_bf16(acc[h * 8 + j], ah, bh[j][0], bh[j][1]);
#pragma unroll
            for (int j = 0; j < 8; j++) mma_bf16(acc[h * 8 + j], ah, bl[j][0], bl[j][1]);
#pragma unroll
            for (int j = 0; j < 8; j++) mma_bf16(acc[h * 8 + j], al, bh[j][0], bh[j][1]);
        }
    }

    int r0 = bm + w * 16 + ly;
#pragma unroll
    for (int nb = 0; nb < 16; nb++) {
        int col = bn + nb * 8 + 2 * lx;
        float b0 = bout[col], b1 = bout[col + 1];
        *reinterpret_cast<float2*>(&out[(size_t)r0 * EMB + col]) =
            make_float2(acc[nb][0] + b0, acc[nb][1] + b1);
        *reinterpret_cast<float2*>(&out[(size_t)(r0 + 8) * EMB + col]) =
            make_float2(acc[nb][2] + b0, acc[nb][3] + b1);
    }
}

// ---------------------------------------------------------------------------
extern "C" void kernel_launch(void* const* d_in, const int* in_sizes, int n_in,
                              void* d_out, int out_size) {
    const float* x     = (const float*)d_in[0];
    const float* W_qkv = (const float*)d_in[1];
    const float* b_qkv = (const float*)d_in[2];
    const float* W_out = (const float*)d_in[3];
    const float* b_out = (const float*)d_in[4];
    float* out = (float*)d_out;

    qkv_tc<<<dim3(MTOT / QBM, H3 / QBN), 256>>>(x, W_qkv, b_qkv);

    cudaFuncSetAttribute(attn_fp16, cudaFuncAttributeMaxDynamicSharedMemorySize, ATT_SMEM);
    attn_fp16<<<dim3(SEQ / BQ, BATCH, 2), 256, ATT_SMEM>>>();

    cudaFuncSetAttribute(out_tc, cudaFuncAttributeMaxDynamicSharedMemorySize, OUT_SMEM);
    out_tc<<<dim3(MTOT / OBM, EMB / OBN), 256, OUT_SMEM>>>(W_out, b_out, out);
}

// round 10
// speedup vs baseline: 5.2907x; 1.2807x over previous
#include <cuda_runtime.h>
#include <cuda_fp16.h>
#include <cuda_bf16.h>
#include <cstdint>

#define BATCH 4
#define SEQ   4096
#define EMB   1024
#define HEAD  64
#define H3    192
#define MTOT  (BATCH*SEQ)   // 16384

// Scratch (allocation-free rule: device globals)
__device__ __align__(16) __half g_q16[MTOT * HEAD];   // q pre-scaled
__device__ __align__(16) __half g_k16[MTOT * HEAD];
__device__ __align__(16) __half g_v16[MTOT * HEAD];
__device__ __align__(16) float  g_po[2][MTOT * HEAD]; // partial O (unnormalized)
__device__ __align__(16) float  g_pm[2][MTOT];
__device__ __align__(16) float  g_pl[2][MTOT];

// ---------------------------------------------------------------------------
// Helpers
// ---------------------------------------------------------------------------
__device__ __forceinline__ float exp2a(float x) {
    float y;
    asm("ex2.approx.f32 %0, %1;" : "=f"(y) : "f"(x));
    return y;
}
__device__ __forceinline__ void mma_bf16(float c[4], const uint32_t a[4],
                                         uint32_t b0, uint32_t b1) {
    asm volatile(
        "mma.sync.aligned.m16n8k16.row.col.f32.bf16.bf16.f32 "
        "{%0,%1,%2,%3}, {%4,%5,%6,%7}, {%8,%9}, {%0,%1,%2,%3};\n"
        : "+f"(c[0]), "+f"(c[1]), "+f"(c[2]), "+f"(c[3])
        : "r"(a[0]), "r"(a[1]), "r"(a[2]), "r"(a[3]), "r"(b0), "r"(b1));
}
__device__ __forceinline__ void mma_f16(float c[4], const uint32_t a[4],
                                        uint32_t b0, uint32_t b1) {
    asm volatile(
        "mma.sync.aligned.m16n8k16.row.col.f32.f16.f16.f32 "
        "{%0,%1,%2,%3}, {%4,%5,%6,%7}, {%8,%9}, {%0,%1,%2,%3};\n"
        : "+f"(c[0]), "+f"(c[1]), "+f"(c[2]), "+f"(c[3])
        : "r"(a[0]), "r"(a[1]), "r"(a[2]), "r"(a[3]), "r"(b0), "r"(b1));
}
__device__ __forceinline__ void split_pack(float x, float y,
                                           uint32_t& hi, uint32_t& lo) {
    __nv_bfloat16 hx = __float2bfloat16_rn(x);
    __nv_bfloat16 hy = __float2bfloat16_rn(y);
    __nv_bfloat16 lxx = __float2bfloat16_rn(x - __bfloat162float(hx));
    __nv_bfloat16 lyy = __float2bfloat16_rn(y - __bfloat162float(hy));
    __nv_bfloat162 h2 = __halves2bfloat162(hx, hy);
    __nv_bfloat162 l2 = __halves2bfloat162(lxx, lyy);
    hi = *reinterpret_cast<uint32_t*>(&h2);
    lo = *reinterpret_cast<uint32_t*>(&l2);
}
__device__ __forceinline__ void ldsm_x4(uint32_t r[4], uint32_t addr) {
    asm volatile("ldmatrix.sync.aligned.m8n8.x4.shared.b16 {%0,%1,%2,%3}, [%4];"
                 : "=r"(r[0]), "=r"(r[1]), "=r"(r[2]), "=r"(r[3]) : "r"(addr));
}
__device__ __forceinline__ void ldsm_x4t(uint32_t r[4], uint32_t addr) {
    asm volatile("ldmatrix.sync.aligned.m8n8.x4.trans.shared.b16 {%0,%1,%2,%3}, [%4];"
                 : "=r"(r[0]), "=r"(r[1]), "=r"(r[2]), "=r"(r[3]) : "r"(addr));
}
__device__ __forceinline__ void cp16(uint32_t dst, const void* src) {
    asm volatile("cp.async.cg.shared.global [%0], [%1], 16;" :: "r"(dst), "l"(src));
}

#define QSCALE (0.125f * 1.44269504088896340736f)   // (1/sqrt(64)) * log2(e)

// ---------------------------------------------------------------------------
// Kernel 1: QKV projection, single-pass fp16 mma (fp32 accumulate).
// C[16384,192] = x[16384,1024] @ W[1024,192] + b, outputs fp16 q/k/v
// (q pre-scaled). BM=128, BN=64, BK=64, 256 threads, ldmatrix fragments,
// register prefetch of the next k-tile.
// ---------------------------------------------------------------------------
#define QST 72   // halves per smem row (144 B) -> conflict-free ldmatrix

__global__ __launch_bounds__(256, 2) void qkv_fp16(const float* __restrict__ x,
                                                   const float* __restrict__ W,
                                                   const float* __restrict__ bias) {
    __shared__ __half sA[128 * QST];   // [m][k] 18432 B
    __shared__ __half sB[64 * QST];    // [n][k]  9216 B

    const int bm = blockIdx.x * 128;
    const int bn = blockIdx.y * 64;    // 0=q, 64=k, 128=v
    const int tid = threadIdx.x;
    const int w = tid >> 5;
    const int lane = tid & 31;
    const int ly = lane >> 2;
    const int lx = lane & 3;

    const uint32_t bA = (uint32_t)__cvta_generic_to_shared(sA);
    const uint32_t bB = (uint32_t)__cvta_generic_to_shared(sB);

    // fragment addresses (attention-proven pattern)
    const int ar = (lane & 7) + ((lane >> 3) & 1) * 8;   // A frag row
    const uint32_t aA = bA + (w * 16 + ar) * 144 + (lane >> 4) * 16;
    const int krB = ((lane >> 4) & 1) * 8 + (lane & 7);  // B frag row (n)
    const int kcB = (lane >> 3) & 1;
    const uint32_t aB = bB + krB * 144 + kcB * 16;

    // B load mapping: n = tid&63, kg = tid>>6 (16 k each)
    const int bn_t = tid & 63;
    const int bkg  = tid >> 6;

    float acc[8][4] = {};

    // prefetch k-tile 0
    float4 ra[8];
    float rb[16];
#pragma unroll
    for (int i = 0; i < 8; i++) {
        int f4 = tid + i * 256;
        ra[i] = *reinterpret_cast<const float4*>(
            x + (size_t)(bm + (f4 >> 4)) * EMB + (f4 & 15) * 4);
    }
    {
        const float* wp = W + (size_t)(bkg * 16) * H3 + bn + bn_t;
#pragma unroll
        for (int j = 0; j < 16; j++) rb[j] = wp[(size_t)j * H3];
    }

    for (int k0 = 0; k0 < EMB; k0 += 64) {
        // store staged regs -> smem fp16
#pragma unroll
        for (int i = 0; i < 8; i++) {
            int f4 = tid + i * 256;
            int row = f4 >> 4;
            int c4 = f4 & 15;
            __half2 h0 = __floats2half2_rn(ra[i].x, ra[i].y);
            __half2 h1 = __floats2half2_rn(ra[i].z, ra[i].w);
            *reinterpret_cast<__half2*>(&sA[row * QST + c4 * 4 + 0]) = h0;
            *reinterpret_cast<__half2*>(&sA[row * QST + c4 * 4 + 2]) = h1;
        }
        {
            uint32_t h[8];
#pragma unroll
            for (int j = 0; j < 8; j++) {
                __half2 p = __floats2half2_rn(rb[2 * j], rb[2 * j + 1]);
                h[j] = *reinterpret_cast<uint32_t*>(&p);
            }
            uint4* dst = reinterpret_cast<uint4*>(&sB[bn_t * QST + bkg * 16]);
            dst[0] = make_uint4(h[0], h[1], h[2], h[3]);
            dst[1] = make_uint4(h[4], h[5], h[6], h[7]);
        }
        __syncthreads();

        // prefetch next tile (overlaps mma)
        if (k0 + 64 < EMB) {
#pragma unroll
            for (int i = 0; i < 8; i++) {
                int f4 = tid + i * 256;
                ra[i] = *reinterpret_cast<const float4*>(
                    x + (size_t)(bm + (f4 >> 4)) * EMB + (k0 + 64) + (f4 & 15) * 4);
            }
            const float* wp = W + (size_t)(k0 + 64 + bkg * 16) * H3 + bn + bn_t;
#pragma unroll
            for (int j = 0; j < 16; j++) rb[j] = wp[(size_t)j * H3];
        }

        // A fragments for 4 k16-steps
        uint32_t Aa[4][4];
#pragma unroll
        for (int ks = 0; ks < 4; ks++) ldsm_x4(Aa[ks], aA + ks * 32);

#pragma unroll
        for (int ks = 0; ks < 4; ks++) {
#pragma unroll
            for (int p = 0; p < 4; p++) {
                uint32_t bb[4];
                ldsm_x4(bb, aB + p * 2304 + ks * 32);   // 2304 = 16*144
                mma_f16(acc[2 * p    ], Aa[ks], bb[0], bb[1]);
                mma_f16(acc[2 * p + 1], Aa[ks], bb[2], bb[3]);
            }
        }
        __syncthreads();
    }

    // epilogue: fp16 outputs (q pre-scaled)
    __half* dst = (blockIdx.y == 0) ? g_q16 : (blockIdx.y == 1) ? g_k16 : g_v16;
    const float sc = (blockIdx.y == 0) ? QSCALE : 1.0f;
    int r0 = bm + w * 16 + ly;
#pragma unroll
    for (int nb = 0; nb < 8; nb++) {
        int col = nb * 8 + 2 * lx;
        float b0 = bias[bn + col], b1 = bias[bn + col + 1];
        __half2 h0 = __floats2half2_rn((acc[nb][0] + b0) * sc, (acc[nb][1] + b1) * sc);
        __half2 h1 = __floats2half2_rn((acc[nb][2] + b0) * sc, (acc[nb][3] + b1) * sc);
        *reinterpret_cast<__half2*>(&dst[(size_t)r0 * HEAD + col]) = h0;
        *reinterpret_cast<__half2*>(&dst[(size_t)(r0 + 8) * HEAD + col]) = h1;
    }
}

// ---------------------------------------------------------------------------
// Kernel 2: fp16 flash attention, split-KV (z), cp.async double-buffered K/V,
// ldmatrix for all fragments (trans for V). BQ=128, KV tiles of 64. Unchanged.
// ---------------------------------------------------------------------------
#define BQ     128
#define PSTR   72
#define KVHALF (SEQ / 2)
#define NTILE  (KVHALF / 64)
#define ATT_SMEM (4 * 64 * PSTR * 2 + 128 * PSTR * 2)   // 55296 B

__global__ __launch_bounds__(256, 2) void attn_fp16() {
    extern __shared__ __half smh[];
    __half* sPQ = smh + 4 * 64 * PSTR;

    const int b    = blockIdx.y;
    const int q0   = blockIdx.x * BQ;
    const int z    = blockIdx.z;
    const int tid  = threadIdx.x;
    const int w    = tid >> 5;
    const int lane = tid & 31;
    const int ly   = lane >> 2;
    const int lx   = lane & 3;

    __half* sPw = sPQ + w * 16 * PSTR;

    const uint32_t smb = (uint32_t)__cvta_generic_to_shared(smh);
    const uint32_t bK  = smb;
    const uint32_t bV  = smb + 2 * 64 * 144;
    const uint32_t bPQ = smb + 4 * 64 * 144;

    const int srow = tid >> 2;
    const int sc   = (tid & 3) * 2;
    const uint32_t dK0 = bK + srow * 144 + sc * 16;
    const uint32_t dV0 = bV + srow * 144 + sc * 16;
    const size_t gb = (size_t)b * SEQ * HEAD;
    const int kv_beg = z * KVHALF;

    {
        const __half* ks = g_k16 + gb + (size_t)(kv_beg + srow) * HEAD + sc * 8;
        const __half* vs = g_v16 + gb + (size_t)(kv_beg + srow) * HEAD + sc * 8;
        cp16(dK0, ks); cp16(dK0 + 16, ks + 8);
        cp16(dV0, vs); cp16(dV0 + 16, vs + 8);
        asm volatile("cp.async.commit_group;");
    }

#pragma unroll
    for (int i = 0; i < 4; i++) {
        int idx = tid + i * 256;
        int row = idx >> 3, c = idx & 7;
        uint4 v = *reinterpret_cast<const uint4*>(
            g_q16 + gb + (size_t)(q0 + row) * HEAD + c * 8);
        *reinterpret_cast<uint4*>(
            reinterpret_cast<char*>(sPQ) + row * 144 + c * 16) = v;
    }
    __syncthreads();

    uint32_t Aq[4][4];
    {
        const int qr = (lane & 7) + ((lane >> 3) & 1) * 8;
        const int qc = lane >> 4;
        uint32_t aQ = bPQ + (w * 16 + qr) * 144 + qc * 16;
#pragma unroll
        for (int ks = 0; ks < 4; ks++) ldsm_x4(Aq[ks], aQ + ks * 32);
    }

    float O[8][4];
    float mrow0 = -1e30f, mrow1 = -1e30f, lrow0 = 0.f, lrow1 = 0.f;
#pragma unroll
    for (int nb = 0; nb < 8; nb++)
#pragma unroll
        for (int j = 0; j < 4; j++) O[nb][j] = 0.f;

    const int krB = ((lane >> 4) & 1) * 8 + (lane & 7);
    const int kcB = (lane >> 3) & 1;
    const int vr  = lane & 15, vc = lane >> 4;
    const int pr  = (lane & 7) + ((lane >> 3) & 1) * 8;
    const uint32_t aP = bPQ + (w * 16 + pr) * 144 + (lane >> 4) * 16;

    for (int t = 0; t < NTILE; t++) {
        const int s = t & 1;
        if (t + 1 < NTILE) {
            const uint32_t off = ((t + 1) & 1) * 64 * 144;
            const __half* ks = g_k16 + gb + (size_t)(kv_beg + (t + 1) * 64 + srow) * HEAD + sc * 8;
            const __half* vs = g_v16 + gb + (size_t)(kv_beg + (t + 1) * 64 + srow) * HEAD + sc * 8;
            cp16(dK0 + off, ks); cp16(dK0 + off + 16, ks + 8);
            cp16(dV0 + off, vs); cp16(dV0 + off + 16, vs + 8);
            asm volatile("cp.async.commit_group;");
            asm volatile("cp.async.wait_group 1;");
        } else {
            asm volatile("cp.async.wait_group 0;");
        }
        __syncthreads();

        const uint32_t aK = bK + s * 64 * 144 + krB * 144 + kcB * 16;
        float S[8][4];
#pragma unroll
        for (int nb = 0; nb < 8; nb++)
#pragma unroll
            for (int j = 0; j < 4; j++) S[nb][j] = 0.f;
#pragma unroll
        for (int ks = 0; ks < 4; ks++)
#pragma unroll
            for (int p = 0; p < 4; p++) {
                uint32_t bb[4];
                ldsm_x4(bb, aK + p * 2304 + ks * 32);
                mma_f16(S[2 * p    ], Aq[ks], bb[0], bb[1]);
                mma_f16(S[2 * p + 1], Aq[ks], bb[2], bb[3]);
            }

        float mt0 = -1e30f, mt1 = -1e30f;
#pragma unroll
        for (int nb = 0; nb < 8; nb++) {
            mt0 = fmaxf(mt0, fmaxf(S[nb][0], S[nb][1]));
            mt1 = fmaxf(mt1, fmaxf(S[nb][2], S[nb][3]));
        }
        mt0 = fmaxf(mt0, __shfl_xor_sync(0xffffffffu, mt0, 1));
        mt0 = fmaxf(mt0, __shfl_xor_sync(0xffffffffu, mt0, 2));
        mt1 = fmaxf(mt1, __shfl_xor_sync(0xffffffffu, mt1, 1));
        mt1 = fmaxf(mt1, __shfl_xor_sync(0xffffffffu, mt1, 2));

        float mn0 = fmaxf(mrow0, mt0);
        float mn1 = fmaxf(mrow1, mt1);
        float corr0 = exp2a(mrow0 - mn0);
        float corr1 = exp2a(mrow1 - mn1);

        float rs0 = 0.f, rs1 = 0.f;
#pragma unroll
        for (int nb = 0; nb < 8; nb++) {
            S[nb][0] = exp2a(S[nb][0] - mn0);
            S[nb][1] = exp2a(S[nb][1] - mn0);
            S[nb][2] = exp2a(S[nb][2] - mn1);
            S[nb][3] = exp2a(S[nb][3] - mn1);
            rs0 += S[nb][0] + S[nb][1];
            rs1 += S[nb][2] + S[nb][3];
        }
        rs0 += __shfl_xor_sync(0xffffffffu, rs0, 1);
        rs0 += __shfl_xor_sync(0xffffffffu, rs0, 2);
        rs1 += __shfl_xor_sync(0xffffffffu, rs1, 1);
        rs1 += __shfl_xor_sync(0xffffffffu, rs1, 2);

        lrow0 = lrow0 * corr0 + rs0;
        lrow1 = lrow1 * corr1 + rs1;
        mrow0 = mn0;
        mrow1 = mn1;

#pragma unroll
        for (int nb = 0; nb < 8; nb++) {
            O[nb][0] *= corr0;
            O[nb][1] *= corr0;
            O[nb][2] *= corr1;
            O[nb][3] *= corr1;
        }

#pragma unroll
        for (int nb = 0; nb < 8; nb++) {
            *reinterpret_cast<__half2*>(&sPw[ly * PSTR + nb * 8 + 2 * lx]) =
                __floats2half2_rn(S[nb][0], S[nb][1]);
            *reinterpret_cast<__half2*>(&sPw[(ly + 8) * PSTR + nb * 8 + 2 * lx]) =
                __floats2half2_rn(S[nb][2], S[nb][3]);
        }
        __syncwarp();

        const uint32_t aV = bV + s * 64 * 144 + vr * 144 + vc * 16;
#pragma unroll
        for (int ks = 0; ks < 4; ks++) {
            uint32_t pa[4];
            ldsm_x4(pa, aP + ks * 32);
#pragma unroll
            for (int p = 0; p < 4; p++) {
                uint32_t bb[4];
                ldsm_x4t(bb, aV + ks * 2304 + p * 32);
                mma_f16(O[2 * p    ], pa, bb[0], bb[1]);
                mma_f16(O[2 * p + 1], pa, bb[2], bb[3]);
            }
        }
        __syncthreads();
    }

    int r0g = b * SEQ + q0 + w * 16 + ly;
#pragma unroll
    for (int nb = 0; nb < 8; nb++) {
        *reinterpret_cast<float2*>(&g_po[z][(size_t)r0g * HEAD + nb * 8 + 2 * lx]) =
            make_float2(O[nb][0], O[nb][1]);
        *reinterpret_cast<float2*>(&g_po[z][(size_t)(r0g + 8) * HEAD + nb * 8 + 2 * lx]) =
            make_float2(O[nb][2], O[nb][3]);
    }
    if (lx == 0) {
        g_pm[z][r0g] = mrow0;      g_pl[z][r0g] = lrow0;
        g_pm[z][r0g + 8] = mrow1;  g_pl[z][r0g + 8] = lrow1;
    }
}

// ---------------------------------------------------------------------------
// Kernel 3: output projection (bf16 3-term split) with fused split-KV combine.
// Unchanged.
// ---------------------------------------------------------------------------
#define OBM 128
#define OBN 128
#define OST 36
#define OUT_SMEM (4 * 128 * OST * 4)

__global__ __launch_bounds__(256) void out_tc(const float* __restrict__ Wout,
                                              const float* __restrict__ bout,
                                              float* __restrict__ out) {
    extern __shared__ uint32_t osm[];
    uint32_t* Ah = osm;
    uint32_t* Al = Ah + OBM * OST;
    uint32_t* Bh = Al + OBM * OST;
    uint32_t* Bl = Bh + OBN * OST;

    const int bm = blockIdx.x * OBM;
    const int bn = blockIdx.y * OBN;
    const int tid = threadIdx.x;
    const int w = tid >> 5;
    const int lane = tid & 31;
    const int ly = lane >> 2;
    const int lx = lane & 3;

#pragma unroll
    for (int i = 0; i < 8; i++) {
        int f4 = tid + i * 256;
        int row = f4 >> 4;
        int c4 = f4 & 15;
        int rg = bm + row;
        float m0 = g_pm[0][rg], m1 = g_pm[1][rg];
        float mx = fmaxf(m0, m1);
        float w0 = exp2a(m0 - mx), w1 = exp2a(m1 - mx);
        float inv = 1.f / (w0 * g_pl[0][rg] + w1 * g_pl[1][rg]);
        float4 a = *reinterpret_cast<const float4*>(&g_po[0][(size_t)rg * HEAD + c4 * 4]);
        float4 c = *reinterpret_cast<const float4*>(&g_po[1][(size_t)rg * HEAD + c4 * 4]);
        float vx = (w0 * a.x + w1 * c.x) * inv;
        float vy = (w0 * a.y + w1 * c.y) * inv;
        float vz = (w0 * a.z + w1 * c.z) * inv;
        float vw = (w0 * a.w + w1 * c.w) * inv;
        uint32_t h0, l0, h1, l1;
        split_pack(vx, vy, h0, l0);
        split_pack(vz, vw, h1, l1);
        Ah[row * OST + 2 * c4 + 0] = h0;
        Al[row * OST + 2 * c4 + 0] = l0;
        Ah[row * OST + 2 * c4 + 1] = h1;
        Al[row * OST + 2 * c4 + 1] = l1;
    }
    {
        int n  = tid & 127;
        int kg = tid >> 7;
        const float* wp = Wout + (size_t)(kg * 32) * EMB + bn + n;
#pragma unroll
        for (int m = 0; m < 16; m++) {
            float f0 = wp[(size_t)(2 * m    ) * EMB];
            float f1 = wp[(size_t)(2 * m + 1) * EMB];
            uint32_t h, l;
            split_pack(f0, f1, h, l);
            Bh[n * OST + kg * 16 + m] = h;
            Bl[n * OST + kg * 16 + m] = l;
        }
    }
    __syncthreads();

    float acc[16][4] = {};
#pragma unroll
    for (int ks = 0; ks < 4; ks++) {
        uint32_t ah[4], al[4];
        int ab = (w * 16 + ly) * OST + ks * 8 + lx;
        ah[0] = Ah[ab];               al[0] = Al[ab];
        ah[1] = Ah[ab + 8 * OST];     al[1] = Al[ab + 8 * OST];
        ah[2] = Ah[ab + 4];           al[2] = Al[ab + 4];
        ah[3] = Ah[ab + 8 * OST + 4]; al[3] = Al[ab + 8 * OST + 4];
#pragma unroll
        for (int h = 0; h < 2; h++) {
            uint32_t bh[8][2], bl[8][2];
#pragma unroll
            for (int j = 0; j < 8; j++) {
                int nb = h * 8 + j;
                int bi = (nb * 8 + ly) * OST + ks * 8 + lx;
                bh[j][0] = Bh[bi]; bh[j][1] = Bh[bi + 4];
                bl[j][0] = Bl[bi]; bl[j][1] = Bl[bi + 4];
            }
#pragma unroll
            for (int j = 0; j < 8; j++) mma_bf16(acc[h * 8 + j], ah, bh[j][0], bh[j][1]);
#pragma unroll
            for (int j = 0; j < 8; j++) mma_bf16(acc[h * 8 + j], ah, bl[j][0], bl[j][1]);
#pragma unroll
            for (int j = 0; j < 8; j++) mma_bf16(acc[h * 8 + j], al, bh[j][0], bh[j][1]);
        }
    }

    int r0 = bm + w * 16 + ly;
#pragma unroll
    for (int nb = 0; nb < 16; nb++) {
        int col = bn + nb * 8 + 2 * lx;
        float b0 = bout[col], b1 = bout[col + 1];
        *reinterpret_cast<float2*>(&out[(size_t)r0 * EMB + col]) =
            make_float2(acc[nb][0] + b0, acc[nb][1] + b1);
        *reinterpret_cast<float2*>(&out[(size_t)(r0 + 8) * EMB + col]) =
            make_float2(acc[nb][2] + b0, acc[nb][3] + b1);
    }
}

// ---------------------------------------------------------------------------
extern "C" void kernel_launch(void* const* d_in, const int* in_sizes, int n_in,
                              void* d_out, int out_size) {
    const float* x     = (const float*)d_in[0];
    const float* W_qkv = (const float*)d_in[1];
    const float* b_qkv = (const float*)d_in[2];
    const float* W_out = (const float*)d_in[3];
    const float* b_out = (const float*)d_in[4];
    float* out = (float*)d_out;

    qkv_fp16<<<dim3(MTOT / 128, 3), 256>>>(x, W_qkv, b_qkv);

    cudaFuncSetAttribute(attn_fp16, cudaFuncAttributeMaxDynamicSharedMemorySize, ATT_SMEM);
    attn_fp16<<<dim3(SEQ / BQ, BATCH, 2), 256, ATT_SMEM>>>();

    cudaFuncSetAttribute(out_tc, cudaFuncAttributeMaxDynamicSharedMemorySize, OUT_SMEM);
    out_tc<<<dim3(MTOT / OBM, EMB / OBN), 256, OUT_SMEM>>>(W_out, b_out, out);
}

// round 11
// speedup vs baseline: 6.2823x; 1.1874x over previous
#include <cuda_runtime.h>
#include <cuda_fp16.h>
#include <cstdint>

#define BATCH 4
#define SEQ   4096
#define EMB   1024
#define HEAD  64
#define H3    192
#define MTOT  (BATCH*SEQ)   // 16384

// Scratch (allocation-free rule: device globals)
__device__ __align__(16) __half g_q16[MTOT * HEAD];   // q pre-scaled
__device__ __align__(16) __half g_k16[MTOT * HEAD];
__device__ __align__(16) __half g_v16[MTOT * HEAD];
__device__ __align__(16) float  g_po[2][MTOT * HEAD]; // partial O (unnormalized)
__device__ __align__(16) float  g_pm[2][MTOT];
__device__ __align__(16) float  g_pl[2][MTOT];

// ---------------------------------------------------------------------------
// Helpers
// ---------------------------------------------------------------------------
__device__ __forceinline__ float exp2a(float x) {
    float y;
    asm("ex2.approx.f32 %0, %1;" : "=f"(y) : "f"(x));
    return y;
}
__device__ __forceinline__ void mma_f16(float c[4], const uint32_t a[4],
                                        uint32_t b0, uint32_t b1) {
    asm volatile(
        "mma.sync.aligned.m16n8k16.row.col.f32.f16.f16.f32 "
        "{%0,%1,%2,%3}, {%4,%5,%6,%7}, {%8,%9}, {%0,%1,%2,%3};\n"
        : "+f"(c[0]), "+f"(c[1]), "+f"(c[2]), "+f"(c[3])
        : "r"(a[0]), "r"(a[1]), "r"(a[2]), "r"(a[3]), "r"(b0), "r"(b1));
}
__device__ __forceinline__ void ldsm_x4(uint32_t r[4], uint32_t addr) {
    asm volatile("ldmatrix.sync.aligned.m8n8.x4.shared.b16 {%0,%1,%2,%3}, [%4];"
                 : "=r"(r[0]), "=r"(r[1]), "=r"(r[2]), "=r"(r[3]) : "r"(addr));
}
__device__ __forceinline__ void ldsm_x4t(uint32_t r[4], uint32_t addr) {
    asm volatile("ldmatrix.sync.aligned.m8n8.x4.trans.shared.b16 {%0,%1,%2,%3}, [%4];"
                 : "=r"(r[0]), "=r"(r[1]), "=r"(r[2]), "=r"(r[3]) : "r"(addr));
}
__device__ __forceinline__ void cp16(uint32_t dst, const void* src) {
    asm volatile("cp.async.cg.shared.global [%0], [%1], 16;" :: "r"(dst), "l"(src));
}
__device__ __forceinline__ uint32_t packh2(float x, float y) {
    __half2 h = __floats2half2_rn(x, y);
    return *reinterpret_cast<uint32_t*>(&h);
}

#define QSCALE (0.125f * 1.44269504088896340736f)   // (1/sqrt(64)) * log2(e)

// ---------------------------------------------------------------------------
// Kernel 1: QKV projection, fp16 mma, double-buffered smem (1 sync/tile),
// grid (3, M/128) so the 3 output-type blocks share x via L2.
// ---------------------------------------------------------------------------
#define QBUF 27648                       // bytes per buffer: (128+64)*144
#define QKV_SMEM (2 * QBUF)              // 55296 B

__global__ __launch_bounds__(256, 2) void qkv_fp16(const float* __restrict__ x,
                                                   const float* __restrict__ W,
                                                   const float* __restrict__ bias) {
    extern __shared__ __half qsm[];

    const int bn = blockIdx.x * 64;    // 0=q, 64=k, 128=v  (fast grid dim!)
    const int bm = blockIdx.y * 128;
    const int tid = threadIdx.x;
    const int w = tid >> 5;
    const int lane = tid & 31;
    const int ly = lane >> 2;
    const int lx = lane & 3;

    const uint32_t smb = (uint32_t)__cvta_generic_to_shared(qsm);

    // fragment offsets within a buffer (A at 0, B at 18432)
    const int ar = (lane & 7) + ((lane >> 3) & 1) * 8;
    const uint32_t offA = (w * 16 + ar) * 144 + (lane >> 4) * 16;
    const int krB = ((lane >> 4) & 1) * 8 + (lane & 7);
    const int kcB = (lane >> 3) & 1;
    const uint32_t offB = 18432 + krB * 144 + kcB * 16;

    const int bn_t = tid & 63;
    const int bkg  = tid >> 6;

    float acc[8][4] = {};

    float4 ra[8];
    float rb[16];
#pragma unroll
    for (int i = 0; i < 8; i++) {
        int f4 = tid + i * 256;
        ra[i] = *reinterpret_cast<const float4*>(
            x + (size_t)(bm + (f4 >> 4)) * EMB + (f4 & 15) * 4);
    }
    {
        const float* wp = W + (size_t)(bkg * 16) * H3 + bn + bn_t;
#pragma unroll
        for (int j = 0; j < 16; j++) rb[j] = wp[(size_t)j * H3];
    }

    for (int k0 = 0; k0 < EMB; k0 += 64) {
        const int p = (k0 >> 6) & 1;
        __half* sA = qsm + p * (QBUF / 2);            // halves: p*13824
        __half* sB = sA + 128 * 72;

        // stage regs -> smem fp16 (A as STS.64, B as 2x STS.128)
#pragma unroll
        for (int i = 0; i < 8; i++) {
            int f4 = tid + i * 256;
            int row = f4 >> 4;
            int c4 = f4 & 15;
            uint2 pk = make_uint2(packh2(ra[i].x, ra[i].y), packh2(ra[i].z, ra[i].w));
            *reinterpret_cast<uint2*>(&sA[row * 72 + c4 * 4]) = pk;
        }
        {
            uint32_t h[8];
#pragma unroll
            for (int j = 0; j < 8; j++) h[j] = packh2(rb[2 * j], rb[2 * j + 1]);
            uint4* dst = reinterpret_cast<uint4*>(&sB[bn_t * 72 + bkg * 16]);
            dst[0] = make_uint4(h[0], h[1], h[2], h[3]);
            dst[1] = make_uint4(h[4], h[5], h[6], h[7]);
        }
        __syncthreads();

        // prefetch next k-tile (overlaps mma)
        if (k0 + 64 < EMB) {
#pragma unroll
            for (int i = 0; i < 8; i++) {
                int f4 = tid + i * 256;
                ra[i] = *reinterpret_cast<const float4*>(
                    x + (size_t)(bm + (f4 >> 4)) * EMB + (k0 + 64) + (f4 & 15) * 4);
            }
            const float* wp = W + (size_t)(k0 + 64 + bkg * 16) * H3 + bn + bn_t;
#pragma unroll
            for (int j = 0; j < 16; j++) rb[j] = wp[(size_t)j * H3];
        }

        const uint32_t bufb = smb + p * QBUF;
        uint32_t Aa[4][4];
#pragma unroll
        for (int ks = 0; ks < 4; ks++) ldsm_x4(Aa[ks], bufb + offA + ks * 32);

#pragma unroll
        for (int ks = 0; ks < 4; ks++) {
#pragma unroll
            for (int q = 0; q < 4; q++) {
                uint32_t bb[4];
                ldsm_x4(bb, bufb + offB + q * 2304 + ks * 32);
                mma_f16(acc[2 * q    ], Aa[ks], bb[0], bb[1]);
                mma_f16(acc[2 * q + 1], Aa[ks], bb[2], bb[3]);
            }
        }
    }

    __half* dst = (blockIdx.x == 0) ? g_q16 : (blockIdx.x == 1) ? g_k16 : g_v16;
    const float sc = (blockIdx.x == 0) ? QSCALE : 1.0f;
    int r0 = bm + w * 16 + ly;
#pragma unroll
    for (int nb = 0; nb < 8; nb++) {
        int col = nb * 8 + 2 * lx;
        float b0 = bias[bn + col], b1 = bias[bn + col + 1];
        __half2 h0 = __floats2half2_rn((acc[nb][0] + b0) * sc, (acc[nb][1] + b1) * sc);
        __half2 h1 = __floats2half2_rn((acc[nb][2] + b0) * sc, (acc[nb][3] + b1) * sc);
        *reinterpret_cast<__half2*>(&dst[(size_t)r0 * HEAD + col]) = h0;
        *reinterpret_cast<__half2*>(&dst[(size_t)(r0 + 8) * HEAD + col]) = h1;
    }
}

// ---------------------------------------------------------------------------
// Kernel 2: fp16 flash attention. 3-stage cp.async ring (1 sync/tile),
// register-resident P (C-fragment of S == A-fragment of PV), split-KV (z).
// ---------------------------------------------------------------------------
#define BQ     128
#define KVHALF (SEQ / 2)
#define NTILE  (KVHALF / 64)
#define STG_SZ (2 * 64 * 144)                 // K+V per stage = 18432 B
#define ATT_SMEM (3 * STG_SZ + 128 * 144)     // + Q staging = 73728 B

__global__ __launch_bounds__(256, 2) void attn_fp16() {
    extern __shared__ __half smh[];

    const int b    = blockIdx.y;
    const int q0   = blockIdx.x * BQ;
    const int z    = blockIdx.z;
    const int tid  = threadIdx.x;
    const int w    = tid >> 5;
    const int lane = tid & 31;
    const int ly   = lane >> 2;
    const int lx   = lane & 3;

    const uint32_t smb = (uint32_t)__cvta_generic_to_shared(smh);
    const uint32_t bQ  = smb + 3 * STG_SZ;

    // staging: 4 threads per row, 2 x 16B chunks
    const int srow = tid >> 2;
    const int sc   = (tid & 3) * 2;
    const uint32_t dOff = srow * 144 + sc * 16;        // within-stage K offset
    const size_t gb = (size_t)b * SEQ * HEAD;
    const int kv_beg = z * KVHALF;

    // prologue: prefetch tile 0 -> stage 0
    {
        const __half* ks = g_k16 + gb + (size_t)(kv_beg + srow) * HEAD + sc * 8;
        const __half* vs = g_v16 + gb + (size_t)(kv_beg + srow) * HEAD + sc * 8;
        cp16(smb + dOff, ks); cp16(smb + dOff + 16, ks + 8);
        cp16(smb + 9216 + dOff, vs); cp16(smb + 9216 + dOff + 16, vs + 8);
        asm volatile("cp.async.commit_group;");
    }

    // stage Q
#pragma unroll
    for (int i = 0; i < 4; i++) {
        int idx = tid + i * 256;
        int row = idx >> 3, c = idx & 7;
        uint4 v = *reinterpret_cast<const uint4*>(
            g_q16 + gb + (size_t)(q0 + row) * HEAD + c * 8);
        *reinterpret_cast<uint4*>(
            reinterpret_cast<char*>(smh) + 3 * STG_SZ + row * 144 + c * 16) = v;
    }
    __syncthreads();

    // Q fragments (pre-scaled fp16)
    uint32_t Aq[4][4];
    {
        const int qr = (lane & 7) + ((lane >> 3) & 1) * 8;
        uint32_t aQ = bQ + (w * 16 + qr) * 144 + (lane >> 4) * 16;
#pragma unroll
        for (int ks = 0; ks < 4; ks++) ldsm_x4(Aq[ks], aQ + ks * 32);
    }

    float O[8][4];
    float mrow0 = -1e30f, mrow1 = -1e30f, lrow0 = 0.f, lrow1 = 0.f;
#pragma unroll
    for (int nb = 0; nb < 8; nb++)
#pragma unroll
        for (int j = 0; j < 4; j++) O[nb][j] = 0.f;

    const uint32_t kOff = (((lane >> 4) & 1) * 8 + (lane & 7)) * 144 + ((lane >> 3) & 1) * 16;
    const uint32_t vOff = 9216 + (lane & 15) * 144 + (lane >> 4) * 16;

    for (int t = 0; t < NTILE; t++) {
        const uint32_t stb = smb + (t % 3) * STG_SZ;
        if (t + 1 < NTILE) {
            const uint32_t nstb = smb + ((t + 1) % 3) * STG_SZ;
            const __half* ks = g_k16 + gb + (size_t)(kv_beg + (t + 1) * 64 + srow) * HEAD + sc * 8;
            const __half* vs = g_v16 + gb + (size_t)(kv_beg + (t + 1) * 64 + srow) * HEAD + sc * 8;
            cp16(nstb + dOff, ks); cp16(nstb + dOff + 16, ks + 8);
            cp16(nstb + 9216 + dOff, vs); cp16(nstb + 9216 + dOff + 16, vs + 8);
            asm volatile("cp.async.commit_group;");
            asm volatile("cp.async.wait_group 1;");
        } else {
            asm volatile("cp.async.wait_group 0;");
        }
        __syncthreads();

        // --- S = Q K^T ---
        const uint32_t aK = stb + kOff;
        float S[8][4];
#pragma unroll
        for (int nb = 0; nb < 8; nb++)
#pragma unroll
            for (int j = 0; j < 4; j++) S[nb][j] = 0.f;
#pragma unroll
        for (int ks = 0; ks < 4; ks++)
#pragma unroll
            for (int p = 0; p < 4; p++) {
                uint32_t bb[4];
                ldsm_x4(bb, aK + p * 2304 + ks * 32);
                mma_f16(S[2 * p    ], Aq[ks], bb[0], bb[1]);
                mma_f16(S[2 * p + 1], Aq[ks], bb[2], bb[3]);
            }

        // --- online softmax (base-2; scale folded into Q) ---
        float mt0 = -1e30f, mt1 = -1e30f;
#pragma unroll
        for (int nb = 0; nb < 8; nb++) {
            mt0 = fmaxf(mt0, fmaxf(S[nb][0], S[nb][1]));
            mt1 = fmaxf(mt1, fmaxf(S[nb][2], S[nb][3]));
        }
        mt0 = fmaxf(mt0, __shfl_xor_sync(0xffffffffu, mt0, 1));
        mt0 = fmaxf(mt0, __shfl_xor_sync(0xffffffffu, mt0, 2));
        mt1 = fmaxf(mt1, __shfl_xor_sync(0xffffffffu, mt1, 1));
        mt1 = fmaxf(mt1, __shfl_xor_sync(0xffffffffu, mt1, 2));

        float mn0 = fmaxf(mrow0, mt0);
        float mn1 = fmaxf(mrow1, mt1);
        float corr0 = exp2a(mrow0 - mn0);
        float corr1 = exp2a(mrow1 - mn1);

        float rs0 = 0.f, rs1 = 0.f;
#pragma unroll
        for (int nb = 0; nb < 8; nb++) {
            S[nb][0] = exp2a(S[nb][0] - mn0);
            S[nb][1] = exp2a(S[nb][1] - mn0);
            S[nb][2] = exp2a(S[nb][2] - mn1);
            S[nb][3] = exp2a(S[nb][3] - mn1);
            rs0 += S[nb][0] + S[nb][1];
            rs1 += S[nb][2] + S[nb][3];
        }
        rs0 += __shfl_xor_sync(0xffffffffu, rs0, 1);
        rs0 += __shfl_xor_sync(0xffffffffu, rs0, 2);
        rs1 += __shfl_xor_sync(0xffffffffu, rs1, 1);
        rs1 += __shfl_xor_sync(0xffffffffu, rs1, 2);

        lrow0 = lrow0 * corr0 + rs0;
        lrow1 = lrow1 * corr1 + rs1;
        mrow0 = mn0;
        mrow1 = mn1;

#pragma unroll
        for (int nb = 0; nb < 8; nb++) {
            O[nb][0] *= corr0;
            O[nb][1] *= corr0;
            O[nb][2] *= corr1;
            O[nb][3] *= corr1;
        }

        // --- O += P V : P direct from registers (C-frag == A-frag layout) ---
        const uint32_t aV = stb + vOff;
#pragma unroll
        for (int ks = 0; ks < 4; ks++) {
            uint32_t pa[4];
            pa[0] = packh2(S[2 * ks    ][0], S[2 * ks    ][1]);
            pa[1] = packh2(S[2 * ks    ][2], S[2 * ks    ][3]);
            pa[2] = packh2(S[2 * ks + 1][0], S[2 * ks + 1][1]);
            pa[3] = packh2(S[2 * ks + 1][2], S[2 * ks + 1][3]);
#pragma unroll
            for (int p = 0; p < 4; p++) {
                uint32_t bb[4];
                ldsm_x4t(bb, aV + ks * 2304 + p * 32);
                mma_f16(O[2 * p    ], pa, bb[0], bb[1]);
                mma_f16(O[2 * p + 1], pa, bb[2], bb[3]);
            }
        }
    }

    // epilogue: partial unnormalized O + (m, l)
    int r0g = b * SEQ + q0 + w * 16 + ly;
#pragma unroll
    for (int nb = 0; nb < 8; nb++) {
        *reinterpret_cast<float2*>(&g_po[z][(size_t)r0g * HEAD + nb * 8 + 2 * lx]) =
            make_float2(O[nb][0], O[nb][1]);
        *reinterpret_cast<float2*>(&g_po[z][(size_t)(r0g + 8) * HEAD + nb * 8 + 2 * lx]) =
            make_float2(O[nb][2], O[nb][3]);
    }
    if (lx == 0) {
        g_pm[z][r0g] = mrow0;      g_pl[z][r0g] = lrow0;
        g_pm[z][r0g + 8] = mrow1;  g_pl[z][r0g + 8] = lrow1;
    }
}

// ---------------------------------------------------------------------------
// Kernel 3: output projection, single-pass fp16 mma with fused split-KV
// combine in the A staging. out[16384,1024] = combine(po) @ W_out + b.
// ---------------------------------------------------------------------------
#define OBM 128
#define OBN 128

__global__ __launch_bounds__(256, 2) void out_fp16(const float* __restrict__ Wout,
                                                   const float* __restrict__ bout,
                                                   float* __restrict__ out) {
    __shared__ __half sA[128 * 72];   // [m][k] 18432 B
    __shared__ __half sB[128 * 72];   // [n][k] 18432 B

    const int bm = blockIdx.x * OBM;
    const int bn = blockIdx.y * OBN;
    const int tid = threadIdx.x;
    const int w = tid >> 5;
    const int lane = tid & 31;
    const int ly = lane >> 2;
    const int lx = lane & 3;

    // A: combine partial O halves -> fp16
#pragma unroll
    for (int i = 0; i < 8; i++) {
        int f4 = tid + i * 256;
        int row = f4 >> 4;
        int c4 = f4 & 15;
        int rg = bm + row;
        float m0 = g_pm[0][rg], m1 = g_pm[1][rg];
        float mx = fmaxf(m0, m1);
        float w0 = exp2a(m0 - mx), w1 = exp2a(m1 - mx);
        float inv = 1.f / (w0 * g_pl[0][rg] + w1 * g_pl[1][rg]);
        float4 a = *reinterpret_cast<const float4*>(&g_po[0][(size_t)rg * HEAD + c4 * 4]);
        float4 c = *reinterpret_cast<const float4*>(&g_po[1][(size_t)rg * HEAD + c4 * 4]);
        uint2 pk = make_uint2(
            packh2((w0 * a.x + w1 * c.x) * inv, (w0 * a.y + w1 * c.y) * inv),
            packh2((w0 * a.z + w1 * c.z) * inv, (w0 * a.w + w1 * c.w) * inv));
        *reinterpret_cast<uint2*>(&sA[row * 72 + c4 * 4]) = pk;
    }
    // B: W_out [64 k][1024 n] -> fp16 [n][k]
    {
        int n  = tid & 127;
        int kg = tid >> 7;                 // 0..1, 32 k each
        const float* wp = Wout + (size_t)(kg * 32) * EMB + bn + n;
        uint32_t h[16];
#pragma unroll
        for (int m = 0; m < 16; m++)
            h[m] = packh2(wp[(size_t)(2 * m) * EMB], wp[(size_t)(2 * m + 1) * EMB]);
        uint4* dst = reinterpret_cast<uint4*>(&sB[n * 72 + kg * 32]);
        dst[0] = make_uint4(h[0],  h[1],  h[2],  h[3]);
        dst[1] = make_uint4(h[4],  h[5],  h[6],  h[7]);
        dst[2] = make_uint4(h[8],  h[9],  h[10], h[11]);
        dst[3] = make_uint4(h[12], h[13], h[14], h[15]);
    }
    __syncthreads();

    const uint32_t bA = (uint32_t)__cvta_generic_to_shared(sA);
    const uint32_t bB = (uint32_t)__cvta_generic_to_shared(sB);
    const int ar = (lane & 7) + ((lane >> 3) & 1) * 8;
    const uint32_t aA = bA + (w * 16 + ar) * 144 + (lane >> 4) * 16;
    const int krB = ((lane >> 4) & 1) * 8 + (lane & 7);
    const uint32_t aB = bB + krB * 144 + ((lane >> 3) & 1) * 16;

    uint32_t Aa[4][4];
#pragma unroll
    for (int ks = 0; ks < 4; ks++) ldsm_x4(Aa[ks], aA + ks * 32);

    float acc[16][4] = {};
#pragma unroll
    for (int ks = 0; ks < 4; ks++) {
#pragma unroll
        for (int p = 0; p < 8; p++) {
            uint32_t bb[4];
            ldsm_x4(bb, aB + p * 2304 + ks * 32);
            mma_f16(acc[2 * p    ], Aa[ks], bb[0], bb[1]);
            mma_f16(acc[2 * p + 1], Aa[ks], bb[2], bb[3]);
        }
    }

    int r0 = bm + w * 16 + ly;
#pragma unroll
    for (int nb = 0; nb < 16; nb++) {
        int col = bn + nb * 8 + 2 * lx;
        float b0 = bout[col], b1 = bout[col + 1];
        *reinterpret_cast<float2*>(&out[(size_t)r0 * EMB + col]) =
            make_float2(acc[nb][0] + b0, acc[nb][1] + b1);
        *reinterpret_cast<float2*>(&out[(size_t)(r0 + 8) * EMB + col]) =
            make_float2(acc[nb][2] + b0, acc[nb][3] + b1);
    }
}

// ---------------------------------------------------------------------------
extern "C" void kernel_launch(void* const* d_in, const int* in_sizes, int n_in,
                              void* d_out, int out_size) {
    const float* x     = (const float*)d_in[0];
    const float* W_qkv = (const float*)d_in[1];
    const float* b_qkv = (const float*)d_in[2];
    const float* W_out = (const float*)d_in[3];
    const float* b_out = (const float*)d_in[4];
    float* out = (float*)d_out;

    cudaFuncSetAttribute(qkv_fp16, cudaFuncAttributeMaxDynamicSharedMemorySize, QKV_SMEM);
    qkv_fp16<<<dim3(3, MTOT / 128), 256, QKV_SMEM>>>(x, W_qkv, b_qkv);

    cudaFuncSetAttribute(attn_fp16, cudaFuncAttributeMaxDynamicSharedMemorySize, ATT_SMEM);
    attn_fp16<<<dim3(SEQ / BQ, BATCH, 2), 256, ATT_SMEM>>>();

    out_fp16<<<dim3(MTOT / OBM, EMB / OBN), 256>>>(W_out, b_out, out);
}